// round 1
// baseline (speedup 1.0000x reference)
#include <cuda_runtime.h>

// ---------------- Problem constants ----------------
#define N_TOK (16 * 2048)   // 32768 tokens
#define D_IN  512
#define E_DIM 256
#define H_DIM 1024
#define NE    4
#define RIN   (E_DIM + D_IN)   // 768 router input dim
#define EPSV  1e-10f

// ---------------- GEMM tiling ----------------
#define TM 128
#define TN 128
#define TK 8
#define MAX_TILES (N_TOK / TM + NE)   // 260: worst-case total M-tiles over experts

#define RTOK_PER_BLK 8
#define RBLK (N_TOK / RTOK_PER_BLK)   // 4096 router blocks

// ---------------- Device scratch (no allocs allowed) ----------------
__device__ int   g_gate_idx[N_TOK];
__device__ float g_gate_val[N_TOK];
__device__ int   g_perm[N_TOK];
__device__ int   g_cnt[NE];
__device__ int   g_cur[NE];
__device__ int   g_off[NE + 1];
__device__ int   g_tile_start[NE + 1];
__device__ float g_part_l1[RBLK];
__device__ float g_part_imp[RBLK * NE];
__device__ float g_H[(size_t)N_TOK * H_DIM];   // 128 MB hidden scratch

// ---------------- 0) reset per-call state ----------------
__global__ void zero_kernel() {
    int t = threadIdx.x;
    if (t < NE) { g_cnt[t] = 0; g_cur[t] = 0; }
}

// ---------------- 1) router: logits -> softmax -> top1 + loss partials ----------------
__global__ __launch_bounds__(256) void router_kernel(
    const float* __restrict__ x, const float* __restrict__ emb,
    const float* __restrict__ rw)
{
    __shared__ float s_rw[RIN * NE];           // 12 KB router weights
    __shared__ float s_l1[RTOK_PER_BLK];
    __shared__ float s_imp[RTOK_PER_BLK][NE];

    int t = threadIdx.x;
    for (int i = t; i < RIN * NE; i += blockDim.x) s_rw[i] = rw[i];
    __syncthreads();

    int warp = t >> 5, lane = t & 31;
    int tok = blockIdx.x * RTOK_PER_BLK + warp;

    float acc0 = 0.f, acc1 = 0.f, acc2 = 0.f, acc3 = 0.f;
    const float* er = emb + (size_t)tok * E_DIM;
    const float* xr = x   + (size_t)tok * D_IN;

    #pragma unroll 4
    for (int k = lane; k < E_DIM; k += 32) {
        float v = er[k];
        const float* w = s_rw + k * NE;
        acc0 += v * w[0]; acc1 += v * w[1]; acc2 += v * w[2]; acc3 += v * w[3];
    }
    #pragma unroll 4
    for (int k = lane; k < D_IN; k += 32) {
        float v = xr[k];
        const float* w = s_rw + (E_DIM + k) * NE;
        acc0 += v * w[0]; acc1 += v * w[1]; acc2 += v * w[2]; acc3 += v * w[3];
    }
    #pragma unroll
    for (int o = 16; o; o >>= 1) {
        acc0 += __shfl_xor_sync(0xFFFFFFFFu, acc0, o);
        acc1 += __shfl_xor_sync(0xFFFFFFFFu, acc1, o);
        acc2 += __shfl_xor_sync(0xFFFFFFFFu, acc2, o);
        acc3 += __shfl_xor_sync(0xFFFFFFFFu, acc3, o);
    }

    if (lane == 0) {
        float lg[NE] = {acc0, acc1, acc2, acc3};
        float m = lg[0];
        #pragma unroll
        for (int e = 1; e < NE; e++) m = fmaxf(m, lg[e]);
        float p[NE], s = 0.f;
        #pragma unroll
        for (int e = 0; e < NE; e++) { p[e] = __expf(lg[e] - m); s += p[e]; }
        float inv = 1.f / s;
        float sump = 0.f, sq = 0.f;
        float best = -1.f; int bi = 0;
        #pragma unroll
        for (int e = 0; e < NE; e++) {
            p[e] *= inv;
            sump += p[e];
            sq   += p[e] * p[e];
            if (p[e] > best) { best = p[e]; bi = e; }   // first-max tie-break, like argmax
        }
        g_gate_idx[tok] = bi;
        g_gate_val[tok] = best;
        atomicAdd(&g_cnt[bi], 1);
        s_l1[warp] = sump / (sqrtf(sq) + EPSV);
        #pragma unroll
        for (int e = 0; e < NE; e++) s_imp[warp][e] = p[e];
    }
    __syncthreads();
    if (t == 0) {
        float a = 0.f;
        #pragma unroll
        for (int w = 0; w < RTOK_PER_BLK; w++) a += s_l1[w];
        g_part_l1[blockIdx.x] = a;
    }
    if (t < NE) {
        float a = 0.f;
        #pragma unroll
        for (int w = 0; w < RTOK_PER_BLK; w++) a += s_imp[w][t];
        g_part_imp[blockIdx.x * NE + t] = a;
    }
}

// ---------------- 2) finalize: reduce losses, scan counts, tile offsets ----------------
__global__ void finalize_kernel(float* __restrict__ out, int out_size) {
    __shared__ float sh[256];
    int t = threadIdx.x;
    float v[5] = {0.f, 0.f, 0.f, 0.f, 0.f};
    for (int b = t; b < RBLK; b += 256) {
        v[0] += g_part_l1[b];
        #pragma unroll
        for (int e = 0; e < NE; e++) v[1 + e] += g_part_imp[b * NE + e];
    }
    float res[5];
    #pragma unroll
    for (int q = 0; q < 5; q++) {
        sh[t] = v[q]; __syncthreads();
        for (int s = 128; s; s >>= 1) {
            if (t < s) sh[t] += sh[t + s];
            __syncthreads();
        }
        res[q] = sh[0];
        __syncthreads();
    }
    if (t == 0) {
        float l1 = res[0] / (float)N_TOK;
        float mean = (res[1] + res[2] + res[3] + res[4]) * 0.25f;
        float var = 0.f;
        #pragma unroll
        for (int e = 0; e < NE; e++) {
            float d = res[1 + e] - mean;
            var += d * d;
        }
        var *= 0.25f;
        float imp = var / (mean * mean + EPSV);
        if (out_size >= N_TOK * D_IN + 2) {
            out[N_TOK * D_IN]     = l1;
            out[N_TOK * D_IN + 1] = imp;
        }
        int s = 0, ts = 0;
        #pragma unroll
        for (int e = 0; e < NE; e++) {
            g_off[e] = s;
            g_tile_start[e] = ts;
            s  += g_cnt[e];
            ts += (g_cnt[e] + TM - 1) / TM;
        }
        g_off[NE] = s;
        g_tile_start[NE] = ts;
    }
}

// ---------------- 3) scatter: build per-expert token lists ----------------
__global__ void scatter_kernel() {
    int t = blockIdx.x * blockDim.x + threadIdx.x;
    if (t >= N_TOK) return;
    int e = g_gate_idx[t];
    int pos = atomicAdd(&g_cur[e], 1);
    g_perm[g_off[e] + pos] = t;
}

// ---------------- 4) GEMM1: H = relu(X[perm] @ W1^T + b1) ----------------
__global__ __launch_bounds__(256) void gemm1_kernel(
    const float* __restrict__ X, const float* __restrict__ W1,
    const float* __restrict__ B1)
{
    __shared__ float As[TK][TM];
    __shared__ float Bs[TK][TN];

    int bt = blockIdx.x;
    if (bt >= g_tile_start[NE]) return;
    int e = 0;
    while (bt >= g_tile_start[e + 1]) e++;
    int m0  = (bt - g_tile_start[e]) * TM;
    int cnt = g_cnt[e];
    int off = g_off[e];
    int n0  = blockIdx.y * TN;

    int t  = threadIdx.x;
    int lr = t >> 1;             // 0..127 (tile row)
    int lc = (t & 1) * 4;        // 0 or 4 (k sub-col, float4)
    int tx = t & 15, ty = t >> 4;

    int am = m0 + lr;
    bool avalid = (am < cnt);
    int tok = avalid ? g_perm[off + am] : 0;
    const float* arow = X  + (size_t)tok * D_IN;
    const float* brow = W1 + (size_t)e * H_DIM * D_IN + (size_t)(n0 + lr) * D_IN;

    float acc[8][8];
    #pragma unroll
    for (int i = 0; i < 8; i++)
        #pragma unroll
        for (int j = 0; j < 8; j++) acc[i][j] = 0.f;

    float4 a_reg = avalid ? *(const float4*)(arow + lc) : make_float4(0, 0, 0, 0);
    float4 b_reg = *(const float4*)(brow + lc);

    for (int k0 = 0; k0 < D_IN; k0 += TK) {
        As[lc + 0][lr] = a_reg.x; As[lc + 1][lr] = a_reg.y;
        As[lc + 2][lr] = a_reg.z; As[lc + 3][lr] = a_reg.w;
        Bs[lc + 0][lr] = b_reg.x; Bs[lc + 1][lr] = b_reg.y;
        Bs[lc + 2][lr] = b_reg.z; Bs[lc + 3][lr] = b_reg.w;
        __syncthreads();
        int kn = k0 + TK;
        if (kn < D_IN) {
            a_reg = avalid ? *(const float4*)(arow + kn + lc) : make_float4(0, 0, 0, 0);
            b_reg = *(const float4*)(brow + kn + lc);
        }
        #pragma unroll
        for (int k = 0; k < TK; k++) {
            float a[8], b[8];
            float4 av0 = *(const float4*)&As[k][ty * 8];
            float4 av1 = *(const float4*)&As[k][ty * 8 + 4];
            float4 bv0 = *(const float4*)&Bs[k][tx * 8];
            float4 bv1 = *(const float4*)&Bs[k][tx * 8 + 4];
            a[0]=av0.x; a[1]=av0.y; a[2]=av0.z; a[3]=av0.w;
            a[4]=av1.x; a[5]=av1.y; a[6]=av1.z; a[7]=av1.w;
            b[0]=bv0.x; b[1]=bv0.y; b[2]=bv0.z; b[3]=bv0.w;
            b[4]=bv1.x; b[5]=bv1.y; b[6]=bv1.z; b[7]=bv1.w;
            #pragma unroll
            for (int i = 0; i < 8; i++)
                #pragma unroll
                for (int j = 0; j < 8; j++)
                    acc[i][j] += a[i] * b[j];
        }
        __syncthreads();
    }

    const float* bias = B1 + e * H_DIM + n0 + tx * 8;
    #pragma unroll
    for (int i = 0; i < 8; i++) {
        int m = m0 + ty * 8 + i;
        if (m < cnt) {
            float* hrow = g_H + (size_t)(off + m) * H_DIM + n0 + tx * 8;
            #pragma unroll
            for (int j = 0; j < 8; j++)
                hrow[j] = fmaxf(acc[i][j] + bias[j], 0.f);
        }
    }
}

// ---------------- 5) GEMM2: out[tok] = gate * (H @ W2^T + b2) ----------------
__global__ __launch_bounds__(256) void gemm2_kernel(
    const float* __restrict__ W2, const float* __restrict__ B2,
    float* __restrict__ out)
{
    __shared__ float As[TK][TM];
    __shared__ float Bs[TK][TN];

    int bt = blockIdx.x;
    if (bt >= g_tile_start[NE]) return;
    int e = 0;
    while (bt >= g_tile_start[e + 1]) e++;
    int m0  = (bt - g_tile_start[e]) * TM;
    int cnt = g_cnt[e];
    int off = g_off[e];
    int n0  = blockIdx.y * TN;

    int t  = threadIdx.x;
    int lr = t >> 1;
    int lc = (t & 1) * 4;
    int tx = t & 15, ty = t >> 4;

    int am = m0 + lr;
    bool avalid = (am < cnt);
    const float* arow = g_H + (size_t)(off + (avalid ? am : 0)) * H_DIM;
    const float* brow = W2  + (size_t)e * D_IN * H_DIM + (size_t)(n0 + lr) * H_DIM;

    float acc[8][8];
    #pragma unroll
    for (int i = 0; i < 8; i++)
        #pragma unroll
        for (int j = 0; j < 8; j++) acc[i][j] = 0.f;

    float4 a_reg = avalid ? *(const float4*)(arow + lc) : make_float4(0, 0, 0, 0);
    float4 b_reg = *(const float4*)(brow + lc);

    for (int k0 = 0; k0 < H_DIM; k0 += TK) {
        As[lc + 0][lr] = a_reg.x; As[lc + 1][lr] = a_reg.y;
        As[lc + 2][lr] = a_reg.z; As[lc + 3][lr] = a_reg.w;
        Bs[lc + 0][lr] = b_reg.x; Bs[lc + 1][lr] = b_reg.y;
        Bs[lc + 2][lr] = b_reg.z; Bs[lc + 3][lr] = b_reg.w;
        __syncthreads();
        int kn = k0 + TK;
        if (kn < H_DIM) {
            a_reg = avalid ? *(const float4*)(arow + kn + lc) : make_float4(0, 0, 0, 0);
            b_reg = *(const float4*)(brow + kn + lc);
        }
        #pragma unroll
        for (int k = 0; k < TK; k++) {
            float a[8], b[8];
            float4 av0 = *(const float4*)&As[k][ty * 8];
            float4 av1 = *(const float4*)&As[k][ty * 8 + 4];
            float4 bv0 = *(const float4*)&Bs[k][tx * 8];
            float4 bv1 = *(const float4*)&Bs[k][tx * 8 + 4];
            a[0]=av0.x; a[1]=av0.y; a[2]=av0.z; a[3]=av0.w;
            a[4]=av1.x; a[5]=av1.y; a[6]=av1.z; a[7]=av1.w;
            b[0]=bv0.x; b[1]=bv0.y; b[2]=bv0.z; b[3]=bv0.w;
            b[4]=bv1.x; b[5]=bv1.y; b[6]=bv1.z; b[7]=bv1.w;
            #pragma unroll
            for (int i = 0; i < 8; i++)
                #pragma unroll
                for (int j = 0; j < 8; j++)
                    acc[i][j] += a[i] * b[j];
        }
        __syncthreads();
    }

    const float* bias = B2 + e * D_IN + n0 + tx * 8;
    #pragma unroll
    for (int i = 0; i < 8; i++) {
        int m = m0 + ty * 8 + i;
        if (m < cnt) {
            int tok = g_perm[off + m];
            float gv = g_gate_val[tok];
            float* orow = out + (size_t)tok * D_IN + n0 + tx * 8;
            #pragma unroll
            for (int j = 0; j < 8; j++)
                orow[j] = (acc[i][j] + bias[j]) * gv;
        }
    }
}

// ---------------- launch ----------------
extern "C" void kernel_launch(void* const* d_in, const int* in_sizes, int n_in,
                              void* d_out, int out_size)
{
    const float* x   = (const float*)d_in[0];   // inputs  [B,S,D]
    const float* emb = (const float*)d_in[1];   // embed   [B,S,EDIM]
    const float* rw  = (const float*)d_in[2];   // router_w[RIN,NE]
    const float* w1  = (const float*)d_in[3];   // [NE,H,D]
    const float* b1  = (const float*)d_in[4];   // [NE,H]
    const float* w2  = (const float*)d_in[5];   // [NE,D,H]
    const float* b2  = (const float*)d_in[6];   // [NE,D]
    float* out = (float*)d_out;

    zero_kernel<<<1, 32>>>();
    router_kernel<<<RBLK, 256>>>(x, emb, rw);
    finalize_kernel<<<1, 256>>>(out, out_size);
    scatter_kernel<<<N_TOK / 256, 256>>>();
    gemm1_kernel<<<dim3(MAX_TILES, H_DIM / TN), 256>>>(x, w1, b1);
    gemm2_kernel<<<dim3(MAX_TILES, D_IN / TN), 256>>>(w2, b2, out);
}

// round 4
// speedup vs baseline: 3.0113x; 3.0113x over previous
#include <cuda_runtime.h>
#include <cuda_bf16.h>
#include <cstdint>

// ---------------- Problem constants ----------------
#define N_TOK (16 * 2048)   // 32768 tokens
#define D_IN  512
#define E_DIM 256
#define H_DIM 1024
#define NE    4
#define RIN   (E_DIM + D_IN)
#define EPSV  1e-10f

// ---------------- GEMM tiling ----------------
#define TM 128
#define TN 128
#define KC 64                         // K elements per pipeline chunk (128B/row/plane)
#define STAGES 3
#define MAX_TILES (N_TOK / TM + NE)   // 260 worst-case M-tiles

#define RTOK_PER_BLK 8
#define RBLK (N_TOK / RTOK_PER_BLK)

// ---------------- Shared memory layout ----------------
// Per stage: Ah 16K | Al 16K | Bh 16K | Bl 16K = 64K
#define STAGE_BYTES 65536
#define SM_BIAS  (STAGES * STAGE_BYTES)          // 196608: 128 floats
#define SM_ABASE (SM_BIAS + 512)                 // 128 x int64 row byte offsets
#define SM_TOK   (SM_ABASE + 1024)               // 128 x int
#define SMEM_DYN (SM_TOK + 512)

// ---------------- Device scratch ----------------
__device__ int   g_gate_idx[N_TOK];
__device__ float g_gate_val[N_TOK];
__device__ int   g_perm[N_TOK + 128];
__device__ int   g_cnt[NE];
__device__ int   g_cur[NE];
__device__ int   g_off[NE + 1];
__device__ int   g_tile_start[NE + 1];
__device__ float g_part_l1[RBLK];
__device__ float g_part_imp[RBLK * NE];

__device__ __nv_bfloat16 g_xhi[(size_t)N_TOK * D_IN];
__device__ __nv_bfloat16 g_xlo[(size_t)N_TOK * D_IN];
__device__ __nv_bfloat16 g_w1hi[(size_t)NE * H_DIM * D_IN];
__device__ __nv_bfloat16 g_w1lo[(size_t)NE * H_DIM * D_IN];
__device__ __nv_bfloat16 g_w2hi[(size_t)NE * D_IN * H_DIM];
__device__ __nv_bfloat16 g_w2lo[(size_t)NE * D_IN * H_DIM];
__device__ __nv_bfloat16 g_hhi[(size_t)(N_TOK + 128) * H_DIM];
__device__ __nv_bfloat16 g_hlo[(size_t)(N_TOK + 128) * H_DIM];

// ---------------- PTX helpers (baseline ISA only: sm_80-era) ----------------
__device__ __forceinline__ uint32_t smem_u32(const void* p) {
    uint32_t a;
    asm("{ .reg .u64 t; cvta.to.shared.u64 t, %1; cvt.u32.u64 %0, t; }" : "=r"(a) : "l"(p));
    return a;
}
__device__ __forceinline__ void cp_async16(uint32_t dst, const void* src) {
    asm volatile("cp.async.cg.shared.global [%0], [%1], 16;" :: "r"(dst), "l"(src) : "memory");
}
#define CP_COMMIT() asm volatile("cp.async.commit_group;" ::: "memory")
#define CP_WAIT2()  asm volatile("cp.async.wait_group 2;" ::: "memory")
#define CP_WAIT0()  asm volatile("cp.async.wait_group 0;" ::: "memory")

__device__ __forceinline__ void ldsm4(uint32_t* r, uint32_t addr) {
    asm volatile("ldmatrix.sync.aligned.m8n8.x4.shared.b16 {%0,%1,%2,%3}, [%4];"
        : "=r"(r[0]), "=r"(r[1]), "=r"(r[2]), "=r"(r[3]) : "r"(addr));
}
__device__ __forceinline__ void mma16816(float* c, const uint32_t* a, const uint32_t* b) {
    asm volatile(
        "mma.sync.aligned.m16n8k16.row.col.f32.bf16.bf16.f32 "
        "{%0,%1,%2,%3}, {%4,%5,%6,%7}, {%8,%9}, {%0,%1,%2,%3};"
        : "+f"(c[0]), "+f"(c[1]), "+f"(c[2]), "+f"(c[3])
        : "r"(a[0]), "r"(a[1]), "r"(a[2]), "r"(a[3]), "r"(b[0]), "r"(b[1]));
}
__device__ __forceinline__ uint32_t swz(uint32_t b) { return b ^ ((b >> 3) & 0x70); }

// ---------------- 0) reset per-call state ----------------
__global__ void zero_kernel() {
    int t = threadIdx.x;
    if (t < NE) { g_cnt[t] = 0; g_cur[t] = 0; }
}

// ---------------- split f32 -> bf16 hi/lo planes ----------------
template <int SEL>
__global__ __launch_bounds__(256) void split_kernel(const float4* __restrict__ src, int n4) {
    __nv_bfloat16 *hi, *lo;
    if (SEL == 0)      { hi = g_xhi;  lo = g_xlo;  }
    else if (SEL == 1) { hi = g_w1hi; lo = g_w1lo; }
    else               { hi = g_w2hi; lo = g_w2lo; }
    __nv_bfloat162* h2 = (__nv_bfloat162*)hi;
    __nv_bfloat162* l2 = (__nv_bfloat162*)lo;
    int stride = gridDim.x * blockDim.x;
    for (int i = blockIdx.x * blockDim.x + threadIdx.x; i < n4; i += stride) {
        float4 v = src[i];
        __nv_bfloat16 h0 = __float2bfloat16_rn(v.x);
        __nv_bfloat16 h1 = __float2bfloat16_rn(v.y);
        __nv_bfloat16 h2v = __float2bfloat16_rn(v.z);
        __nv_bfloat16 h3 = __float2bfloat16_rn(v.w);
        __nv_bfloat16 l0 = __float2bfloat16_rn(v.x - __bfloat162float(h0));
        __nv_bfloat16 l1 = __float2bfloat16_rn(v.y - __bfloat162float(h1));
        __nv_bfloat16 l2v = __float2bfloat16_rn(v.z - __bfloat162float(h2v));
        __nv_bfloat16 l3 = __float2bfloat16_rn(v.w - __bfloat162float(h3));
        h2[2 * i]     = __halves2bfloat162(h0, h1);
        h2[2 * i + 1] = __halves2bfloat162(h2v, h3);
        l2[2 * i]     = __halves2bfloat162(l0, l1);
        l2[2 * i + 1] = __halves2bfloat162(l2v, l3);
    }
}

// ---------------- 1) router ----------------
__global__ __launch_bounds__(256) void router_kernel(
    const float* __restrict__ x, const float* __restrict__ emb,
    const float* __restrict__ rw)
{
    __shared__ float s_rw[RIN * NE];
    __shared__ float s_l1[RTOK_PER_BLK];
    __shared__ float s_imp[RTOK_PER_BLK][NE];

    int t = threadIdx.x;
    for (int i = t; i < RIN * NE; i += blockDim.x) s_rw[i] = rw[i];
    __syncthreads();

    int warp = t >> 5, lane = t & 31;
    int tok = blockIdx.x * RTOK_PER_BLK + warp;

    float acc0 = 0.f, acc1 = 0.f, acc2 = 0.f, acc3 = 0.f;
    const float* er = emb + (size_t)tok * E_DIM;
    const float* xr = x   + (size_t)tok * D_IN;

    #pragma unroll 4
    for (int k = lane; k < E_DIM; k += 32) {
        float v = er[k];
        const float* w = s_rw + k * NE;
        acc0 += v * w[0]; acc1 += v * w[1]; acc2 += v * w[2]; acc3 += v * w[3];
    }
    #pragma unroll 4
    for (int k = lane; k < D_IN; k += 32) {
        float v = xr[k];
        const float* w = s_rw + (E_DIM + k) * NE;
        acc0 += v * w[0]; acc1 += v * w[1]; acc2 += v * w[2]; acc3 += v * w[3];
    }
    #pragma unroll
    for (int o = 16; o; o >>= 1) {
        acc0 += __shfl_xor_sync(0xFFFFFFFFu, acc0, o);
        acc1 += __shfl_xor_sync(0xFFFFFFFFu, acc1, o);
        acc2 += __shfl_xor_sync(0xFFFFFFFFu, acc2, o);
        acc3 += __shfl_xor_sync(0xFFFFFFFFu, acc3, o);
    }

    if (lane == 0) {
        float lg[NE] = {acc0, acc1, acc2, acc3};
        float m = lg[0];
        #pragma unroll
        for (int e = 1; e < NE; e++) m = fmaxf(m, lg[e]);
        float p[NE], s = 0.f;
        #pragma unroll
        for (int e = 0; e < NE; e++) { p[e] = __expf(lg[e] - m); s += p[e]; }
        float inv = 1.f / s;
        float sump = 0.f, sq = 0.f;
        float best = -1.f; int bi = 0;
        #pragma unroll
        for (int e = 0; e < NE; e++) {
            p[e] *= inv;
            sump += p[e];
            sq   += p[e] * p[e];
            if (p[e] > best) { best = p[e]; bi = e; }
        }
        g_gate_idx[tok] = bi;
        g_gate_val[tok] = best;
        atomicAdd(&g_cnt[bi], 1);
        s_l1[warp] = sump / (sqrtf(sq) + EPSV);
        #pragma unroll
        for (int e = 0; e < NE; e++) s_imp[warp][e] = p[e];
    }
    __syncthreads();
    if (t == 0) {
        float a = 0.f;
        #pragma unroll
        for (int w = 0; w < RTOK_PER_BLK; w++) a += s_l1[w];
        g_part_l1[blockIdx.x] = a;
    }
    if (t < NE) {
        float a = 0.f;
        #pragma unroll
        for (int w = 0; w < RTOK_PER_BLK; w++) a += s_imp[w][t];
        g_part_imp[blockIdx.x * NE + t] = a;
    }
}

// ---------------- 2) finalize ----------------
__global__ void finalize_kernel(float* __restrict__ out, int out_size) {
    __shared__ float sh[256];
    int t = threadIdx.x;
    float v[5] = {0.f, 0.f, 0.f, 0.f, 0.f};
    for (int b = t; b < RBLK; b += 256) {
        v[0] += g_part_l1[b];
        #pragma unroll
        for (int e = 0; e < NE; e++) v[1 + e] += g_part_imp[b * NE + e];
    }
    float res[5];
    #pragma unroll
    for (int q = 0; q < 5; q++) {
        sh[t] = v[q]; __syncthreads();
        for (int s = 128; s; s >>= 1) {
            if (t < s) sh[t] += sh[t + s];
            __syncthreads();
        }
        res[q] = sh[0];
        __syncthreads();
    }
    if (t == 0) {
        float l1 = res[0] / (float)N_TOK;
        float mean = (res[1] + res[2] + res[3] + res[4]) * 0.25f;
        float var = 0.f;
        #pragma unroll
        for (int e = 0; e < NE; e++) {
            float d = res[1 + e] - mean;
            var += d * d;
        }
        var *= 0.25f;
        float imp = var / (mean * mean + EPSV);
        if (out_size >= N_TOK * D_IN + 2) {
            out[N_TOK * D_IN]     = l1;
            out[N_TOK * D_IN + 1] = imp;
        }
        int s = 0, ts = 0;
        #pragma unroll
        for (int e = 0; e < NE; e++) {
            g_off[e] = s;
            g_tile_start[e] = ts;
            s  += g_cnt[e];
            ts += (g_cnt[e] + TM - 1) / TM;
        }
        g_off[NE] = s;
        g_tile_start[NE] = ts;
    }
}

// ---------------- 3) scatter ----------------
__global__ void scatter_kernel() {
    int t = blockIdx.x * blockDim.x + threadIdx.x;
    if (t >= N_TOK) return;
    int e = g_gate_idx[t];
    int pos = atomicAdd(&g_cur[e], 1);
    g_perm[g_off[e] + pos] = t;
}

// ---------------- 4/5) split-bf16 grouped GEMM via mma.sync ----------------
// FIRST:  H(hi/lo) = relu(X[perm] @ W1^T + b1)    KDIM=512,  NOUT=1024
// !FIRST: out[tok] = gate * (H @ W2^T + b2)       KDIM=1024, NOUT=512
template <int KDIM, int NOUT, bool FIRST>
__global__ __launch_bounds__(256, 1) void moe_gemm(const float* __restrict__ BIAS,
                                                   float* __restrict__ OUT)
{
    extern __shared__ char smem[];
    constexpr int NC = KDIM / KC;

    int bt = blockIdx.x;
    if (bt >= g_tile_start[NE]) return;
    int e = 0;
    while (bt >= g_tile_start[e + 1]) e++;
    int m0  = (bt - g_tile_start[e]) * TM;
    int cnt = g_cnt[e];
    int off = g_off[e];
    int n0  = blockIdx.y * TN;

    uint32_t sb = smem_u32(smem);
    int tid = threadIdx.x, wid = tid >> 5, lane = tid & 31;

    // per-row gmem byte offsets (A gather) + tokens + bias
    if (tid < TM) {
        int am = m0 + tid;
        bool v = am < cnt;
        long rowb;
        int tok = 0;
        if (FIRST) { tok = v ? g_perm[off + am] : 0; rowb = (long)tok * (KDIM * 2); }
        else       { tok = v ? g_perm[off + am] : 0; rowb = (long)(off + (v ? am : 0)) * (KDIM * 2); }
        ((long*)(smem + SM_ABASE))[tid] = rowb;
        ((int*)(smem + SM_TOK))[tid] = tok;
    }
    if (tid < TN) ((float*)(smem + SM_BIAS))[tid] = BIAS[e * NOUT + n0 + tid];

    const char* Ah = FIRST ? (const char*)g_xhi  : (const char*)g_hhi;
    const char* Al = FIRST ? (const char*)g_xlo  : (const char*)g_hlo;
    const char* Bh = (FIRST ? (const char*)g_w1hi : (const char*)g_w2hi)
                     + ((size_t)(e * NOUT + n0)) * (KDIM * 2);
    const char* Bl = (FIRST ? (const char*)g_w1lo : (const char*)g_w2lo)
                     + ((size_t)(e * NOUT + n0)) * (KDIM * 2);
    const long* s_abase = (const long*)(smem + SM_ABASE);

    __syncthreads();   // abase table ready before loads use it

    int lr = tid >> 3, lseg = tid & 7;          // cp.async: 128 rows x 8 segs per plane half?
    // Each plane = 128 rows x 128B = 1024 x 16B ops; 256 threads -> 4 iters/plane.
    auto load_chunk = [&](int c, int s) {
        long k0b = (long)c * (KC * 2);
        uint32_t base = sb + s * STAGE_BYTES;
        #pragma unroll
        for (int i = 0; i < 4; i++) {
            int r = lr + i * 32;
            uint32_t d = swz(r * 128 + lseg * 16);
            long ro = s_abase[r] + k0b + lseg * 16;
            cp_async16(base + d,         Ah + ro);
            cp_async16(base + 16384 + d, Al + ro);
            long rb = (long)r * (KDIM * 2) + k0b + lseg * 16;
            cp_async16(base + 32768 + d, Bh + rb);
            cp_async16(base + 49152 + d, Bl + rb);
        }
    };

    load_chunk(0, 0); CP_COMMIT();
    load_chunk(1, 1); CP_COMMIT();
    load_chunk(2, 2); CP_COMMIT();

    // warp layout: 2 (M) x 4 (N); warp tile 64x32
    int wm = (wid >> 2) * 64;
    int wn = (wid & 3) * 32;
    int a_row = lane & 15;                 // + wm + f*16
    uint32_t a_col = (lane >> 4) * 16;     // byte
    int b_row = wn + ((lane >> 4) << 3) + (lane & 7);   // + p*16
    uint32_t b_col = ((lane >> 3) & 1) * 16;

    float acc[4][4][4];
    #pragma unroll
    for (int i = 0; i < 4; i++)
        #pragma unroll
        for (int j = 0; j < 4; j++)
            #pragma unroll
            for (int k = 0; k < 4; k++) acc[i][j][k] = 0.f;

    for (int c = 0; c < NC; c++) {
        int s = c % STAGES;
        CP_WAIT2();
        __syncthreads();
        uint32_t ahb = sb + s * STAGE_BYTES;
        uint32_t alb = ahb + 16384;
        uint32_t bhb = ahb + 32768;
        uint32_t blb = ahb + 49152;

        #pragma unroll
        for (int ks = 0; ks < 4; ks++) {
            uint32_t kb = ks * 32;   // 16 elems * 2B
            uint32_t ah[4][4], al[4][4], bh[4][2], bl[4][2];
            #pragma unroll
            for (int f = 0; f < 4; f++)
                ldsm4(ah[f], ahb + swz((wm + f * 16 + a_row) * 128 + kb + a_col));
            #pragma unroll
            for (int p = 0; p < 2; p++) {
                uint32_t r[4];
                ldsm4(r, bhb + swz((b_row + p * 16) * 128 + kb + b_col));
                bh[2 * p][0] = r[0]; bh[2 * p][1] = r[1];
                bh[2 * p + 1][0] = r[2]; bh[2 * p + 1][1] = r[3];
            }
            #pragma unroll
            for (int f = 0; f < 4; f++)
                #pragma unroll
                for (int g = 0; g < 4; g++)
                    mma16816(acc[f][g], ah[f], bh[g]);     // hi*hi
            #pragma unroll
            for (int p = 0; p < 2; p++) {
                uint32_t r[4];
                ldsm4(r, blb + swz((b_row + p * 16) * 128 + kb + b_col));
                bl[2 * p][0] = r[0]; bl[2 * p][1] = r[1];
                bl[2 * p + 1][0] = r[2]; bl[2 * p + 1][1] = r[3];
            }
            #pragma unroll
            for (int f = 0; f < 4; f++)
                #pragma unroll
                for (int g = 0; g < 4; g++)
                    mma16816(acc[f][g], ah[f], bl[g]);     // hi*lo
            #pragma unroll
            for (int f = 0; f < 4; f++)
                ldsm4(al[f], alb + swz((wm + f * 16 + a_row) * 128 + kb + a_col));
            #pragma unroll
            for (int f = 0; f < 4; f++)
                #pragma unroll
                for (int g = 0; g < 4; g++)
                    mma16816(acc[f][g], al[f], bh[g]);     // lo*hi
        }
        __syncthreads();
        if (c + STAGES < NC) load_chunk(c + STAGES, s);
        CP_COMMIT();
    }
    CP_WAIT0();

    // ---- epilogue ----
    // acc[f][g][k]: row = wm + f*16 + (k>=2)*8 + lane/4 ; col = wn + g*8 + 2*(lane%4) + (k&1)
    const float* sbias = (const float*)(smem + SM_BIAS);
    const int* s_tok = (const int*)(smem + SM_TOK);
    int rbase = wm + (lane >> 2);
    int cbase = wn + 2 * (lane & 3);

    #pragma unroll
    for (int f = 0; f < 4; f++) {
        #pragma unroll
        for (int half = 0; half < 2; half++) {
            int lrow = rbase + f * 16 + half * 8;
            if (m0 + lrow >= cnt) continue;
            if (FIRST) {
                size_t hrow = (size_t)(off + m0 + lrow) * H_DIM + n0;
                #pragma unroll
                for (int g = 0; g < 4; g++) {
                    int col = cbase + g * 8;
                    float v0 = fmaxf(acc[f][g][2 * half]     + sbias[col],     0.f);
                    float v1 = fmaxf(acc[f][g][2 * half + 1] + sbias[col + 1], 0.f);
                    __nv_bfloat16 h0 = __float2bfloat16_rn(v0);
                    __nv_bfloat16 h1 = __float2bfloat16_rn(v1);
                    *(__nv_bfloat162*)(g_hhi + hrow + col) = __halves2bfloat162(h0, h1);
                    *(__nv_bfloat162*)(g_hlo + hrow + col) = __halves2bfloat162(
                        __float2bfloat16_rn(v0 - __bfloat162float(h0)),
                        __float2bfloat16_rn(v1 - __bfloat162float(h1)));
                }
            } else {
                int tok = s_tok[lrow];
                float gv = g_gate_val[tok];
                float* orow = OUT + (size_t)tok * D_IN + n0;
                #pragma unroll
                for (int g = 0; g < 4; g++) {
                    int col = cbase + g * 8;
                    float2 o;
                    o.x = (acc[f][g][2 * half]     + sbias[col])     * gv;
                    o.y = (acc[f][g][2 * half + 1] + sbias[col + 1]) * gv;
                    *(float2*)(orow + col) = o;
                }
            }
        }
    }
}

// ---------------- launch ----------------
extern "C" void kernel_launch(void* const* d_in, const int* in_sizes, int n_in,
                              void* d_out, int out_size)
{
    const float* x   = (const float*)d_in[0];
    const float* emb = (const float*)d_in[1];
    const float* rw  = (const float*)d_in[2];
    const float* w1  = (const float*)d_in[3];
    const float* b1  = (const float*)d_in[4];
    const float* w2  = (const float*)d_in[5];
    const float* b2  = (const float*)d_in[6];
    float* out = (float*)d_out;

    cudaFuncSetAttribute(moe_gemm<D_IN, H_DIM, true>,
                         cudaFuncAttributeMaxDynamicSharedMemorySize, SMEM_DYN);
    cudaFuncSetAttribute(moe_gemm<H_DIM, D_IN, false>,
                         cudaFuncAttributeMaxDynamicSharedMemorySize, SMEM_DYN);

    zero_kernel<<<1, 32>>>();
    split_kernel<0><<<1024, 256>>>((const float4*)x,  N_TOK * D_IN / 4);
    split_kernel<1><<<512, 256>>>((const float4*)w1, NE * H_DIM * D_IN / 4);
    split_kernel<2><<<512, 256>>>((const float4*)w2, NE * D_IN * H_DIM / 4);
    router_kernel<<<RBLK, 256>>>(x, emb, rw);
    finalize_kernel<<<1, 256>>>(out, out_size);
    scatter_kernel<<<N_TOK / 256, 256>>>();
    moe_gemm<D_IN, H_DIM, true><<<dim3(MAX_TILES, H_DIM / TN), 256, SMEM_DYN>>>(b1, nullptr);
    moe_gemm<H_DIM, D_IN, false><<<dim3(MAX_TILES, D_IN / TN), 256, SMEM_DYN>>>(b2, out);
}

// round 5
// speedup vs baseline: 3.0336x; 1.0074x over previous
#include <cuda_runtime.h>
#include <cuda_bf16.h>
#include <cstdint>

// ---------------- Problem constants ----------------
#define N_TOK (16 * 2048)   // 32768 tokens
#define D_IN  512
#define E_DIM 256
#define H_DIM 1024
#define NE    4
#define RIN   (E_DIM + D_IN)
#define EPSV  1e-10f

// ---------------- GEMM tiling ----------------
#define TM 128
#define TN 256
#define KC 64                         // K elements per pipeline chunk (128B/row/plane)
#define STAGES 2
#define NTHREADS 512
#define MAX_TILES (N_TOK / TM + NE)   // 260 worst-case M-tiles

#define RTOK_PER_BLK 8
#define RBLK (N_TOK / RTOK_PER_BLK)

// ---------------- Shared memory layout ----------------
// Per stage: Ah 16K | Al 16K | Bh 32K | Bl 32K = 96K
#define STAGE_BYTES 98304
#define SM_BIAS  (STAGES * STAGE_BYTES)          // 196608: 256 floats
#define SM_ABASE (SM_BIAS + 1024)                // 128 x int64 row byte offsets
#define SM_TOK   (SM_ABASE + 1024)               // 128 x int
#define SMEM_DYN (SM_TOK + 512)

// ---------------- Device scratch ----------------
__device__ int   g_gate_idx[N_TOK];
__device__ float g_gate_val[N_TOK];
__device__ int   g_perm[N_TOK + 128];
__device__ int   g_cnt[NE];
__device__ int   g_cur[NE];
__device__ int   g_off[NE + 1];
__device__ int   g_tile_start[NE + 1];
__device__ float g_part_l1[RBLK];
__device__ float g_part_imp[RBLK * NE];

__device__ __nv_bfloat16 g_xhi[(size_t)N_TOK * D_IN];
__device__ __nv_bfloat16 g_xlo[(size_t)N_TOK * D_IN];
__device__ __nv_bfloat16 g_w1hi[(size_t)NE * H_DIM * D_IN];
__device__ __nv_bfloat16 g_w1lo[(size_t)NE * H_DIM * D_IN];
__device__ __nv_bfloat16 g_w2hi[(size_t)NE * D_IN * H_DIM];
__device__ __nv_bfloat16 g_w2lo[(size_t)NE * D_IN * H_DIM];
__device__ __nv_bfloat16 g_hhi[(size_t)(N_TOK + 128) * H_DIM];
__device__ __nv_bfloat16 g_hlo[(size_t)(N_TOK + 128) * H_DIM];

// ---------------- PTX helpers (baseline ISA only) ----------------
__device__ __forceinline__ uint32_t smem_u32(const void* p) {
    uint32_t a;
    asm("{ .reg .u64 t; cvta.to.shared.u64 t, %1; cvt.u32.u64 %0, t; }" : "=r"(a) : "l"(p));
    return a;
}
__device__ __forceinline__ void cp_async16(uint32_t dst, const void* src) {
    asm volatile("cp.async.cg.shared.global [%0], [%1], 16;" :: "r"(dst), "l"(src) : "memory");
}
#define CP_COMMIT() asm volatile("cp.async.commit_group;" ::: "memory")
#define CP_WAIT1()  asm volatile("cp.async.wait_group 1;" ::: "memory")
#define CP_WAIT0()  asm volatile("cp.async.wait_group 0;" ::: "memory")

__device__ __forceinline__ void ldsm4(uint32_t* r, uint32_t addr) {
    asm volatile("ldmatrix.sync.aligned.m8n8.x4.shared.b16 {%0,%1,%2,%3}, [%4];"
        : "=r"(r[0]), "=r"(r[1]), "=r"(r[2]), "=r"(r[3]) : "r"(addr));
}
__device__ __forceinline__ void mma16816(float* c, const uint32_t* a, const uint32_t* b) {
    asm volatile(
        "mma.sync.aligned.m16n8k16.row.col.f32.bf16.bf16.f32 "
        "{%0,%1,%2,%3}, {%4,%5,%6,%7}, {%8,%9}, {%0,%1,%2,%3};"
        : "+f"(c[0]), "+f"(c[1]), "+f"(c[2]), "+f"(c[3])
        : "r"(a[0]), "r"(a[1]), "r"(a[2]), "r"(a[3]), "r"(b[0]), "r"(b[1]));
}
__device__ __forceinline__ uint32_t swz(uint32_t b) { return b ^ ((b >> 3) & 0x70); }

// ---------------- 0) reset per-call state ----------------
__global__ void zero_kernel() {
    int t = threadIdx.x;
    if (t < NE) { g_cnt[t] = 0; g_cur[t] = 0; }
}

// ---------------- split f32 -> bf16 hi/lo planes ----------------
template <int SEL>
__global__ __launch_bounds__(256) void split_kernel(const float4* __restrict__ src, int n4) {
    __nv_bfloat16 *hi, *lo;
    if (SEL == 0)      { hi = g_xhi;  lo = g_xlo;  }
    else if (SEL == 1) { hi = g_w1hi; lo = g_w1lo; }
    else               { hi = g_w2hi; lo = g_w2lo; }
    __nv_bfloat162* h2 = (__nv_bfloat162*)hi;
    __nv_bfloat162* l2 = (__nv_bfloat162*)lo;
    int stride = gridDim.x * blockDim.x;
    for (int i = blockIdx.x * blockDim.x + threadIdx.x; i < n4; i += stride) {
        float4 v = src[i];
        __nv_bfloat16 h0 = __float2bfloat16_rn(v.x);
        __nv_bfloat16 h1 = __float2bfloat16_rn(v.y);
        __nv_bfloat16 h2v = __float2bfloat16_rn(v.z);
        __nv_bfloat16 h3 = __float2bfloat16_rn(v.w);
        __nv_bfloat16 l0 = __float2bfloat16_rn(v.x - __bfloat162float(h0));
        __nv_bfloat16 l1 = __float2bfloat16_rn(v.y - __bfloat162float(h1));
        __nv_bfloat16 l2v = __float2bfloat16_rn(v.z - __bfloat162float(h2v));
        __nv_bfloat16 l3 = __float2bfloat16_rn(v.w - __bfloat162float(h3));
        h2[2 * i]     = __halves2bfloat162(h0, h1);
        h2[2 * i + 1] = __halves2bfloat162(h2v, h3);
        l2[2 * i]     = __halves2bfloat162(l0, l1);
        l2[2 * i + 1] = __halves2bfloat162(l2v, l3);
    }
}

// ---------------- 1) router ----------------
__global__ __launch_bounds__(256) void router_kernel(
    const float* __restrict__ x, const float* __restrict__ emb,
    const float* __restrict__ rw)
{
    __shared__ float s_rw[RIN * NE];
    __shared__ float s_l1[RTOK_PER_BLK];
    __shared__ float s_imp[RTOK_PER_BLK][NE];

    int t = threadIdx.x;
    for (int i = t; i < RIN * NE; i += blockDim.x) s_rw[i] = rw[i];
    __syncthreads();

    int warp = t >> 5, lane = t & 31;
    int tok = blockIdx.x * RTOK_PER_BLK + warp;

    float acc0 = 0.f, acc1 = 0.f, acc2 = 0.f, acc3 = 0.f;
    const float* er = emb + (size_t)tok * E_DIM;
    const float* xr = x   + (size_t)tok * D_IN;

    #pragma unroll 4
    for (int k = lane; k < E_DIM; k += 32) {
        float v = er[k];
        const float* w = s_rw + k * NE;
        acc0 += v * w[0]; acc1 += v * w[1]; acc2 += v * w[2]; acc3 += v * w[3];
    }
    #pragma unroll 4
    for (int k = lane; k < D_IN; k += 32) {
        float v = xr[k];
        const float* w = s_rw + (E_DIM + k) * NE;
        acc0 += v * w[0]; acc1 += v * w[1]; acc2 += v * w[2]; acc3 += v * w[3];
    }
    #pragma unroll
    for (int o = 16; o; o >>= 1) {
        acc0 += __shfl_xor_sync(0xFFFFFFFFu, acc0, o);
        acc1 += __shfl_xor_sync(0xFFFFFFFFu, acc1, o);
        acc2 += __shfl_xor_sync(0xFFFFFFFFu, acc2, o);
        acc3 += __shfl_xor_sync(0xFFFFFFFFu, acc3, o);
    }

    if (lane == 0) {
        float lg[NE] = {acc0, acc1, acc2, acc3};
        float m = lg[0];
        #pragma unroll
        for (int e = 1; e < NE; e++) m = fmaxf(m, lg[e]);
        float p[NE], s = 0.f;
        #pragma unroll
        for (int e = 0; e < NE; e++) { p[e] = __expf(lg[e] - m); s += p[e]; }
        float inv = 1.f / s;
        float sump = 0.f, sq = 0.f;
        float best = -1.f; int bi = 0;
        #pragma unroll
        for (int e = 0; e < NE; e++) {
            p[e] *= inv;
            sump += p[e];
            sq   += p[e] * p[e];
            if (p[e] > best) { best = p[e]; bi = e; }
        }
        g_gate_idx[tok] = bi;
        g_gate_val[tok] = best;
        atomicAdd(&g_cnt[bi], 1);
        s_l1[warp] = sump / (sqrtf(sq) + EPSV);
        #pragma unroll
        for (int e = 0; e < NE; e++) s_imp[warp][e] = p[e];
    }
    __syncthreads();
    if (t == 0) {
        float a = 0.f;
        #pragma unroll
        for (int w = 0; w < RTOK_PER_BLK; w++) a += s_l1[w];
        g_part_l1[blockIdx.x] = a;
    }
    if (t < NE) {
        float a = 0.f;
        #pragma unroll
        for (int w = 0; w < RTOK_PER_BLK; w++) a += s_imp[w][t];
        g_part_imp[blockIdx.x * NE + t] = a;
    }
}

// ---------------- 2) finalize ----------------
__global__ void finalize_kernel(float* __restrict__ out, int out_size) {
    __shared__ float sh[256];
    int t = threadIdx.x;
    float v[5] = {0.f, 0.f, 0.f, 0.f, 0.f};
    for (int b = t; b < RBLK; b += 256) {
        v[0] += g_part_l1[b];
        #pragma unroll
        for (int e = 0; e < NE; e++) v[1 + e] += g_part_imp[b * NE + e];
    }
    float res[5];
    #pragma unroll
    for (int q = 0; q < 5; q++) {
        sh[t] = v[q]; __syncthreads();
        for (int s = 128; s; s >>= 1) {
            if (t < s) sh[t] += sh[t + s];
            __syncthreads();
        }
        res[q] = sh[0];
        __syncthreads();
    }
    if (t == 0) {
        float l1 = res[0] / (float)N_TOK;
        float mean = (res[1] + res[2] + res[3] + res[4]) * 0.25f;
        float var = 0.f;
        #pragma unroll
        for (int e = 0; e < NE; e++) {
            float d = res[1 + e] - mean;
            var += d * d;
        }
        var *= 0.25f;
        float imp = var / (mean * mean + EPSV);
        if (out_size >= N_TOK * D_IN + 2) {
            out[N_TOK * D_IN]     = l1;
            out[N_TOK * D_IN + 1] = imp;
        }
        int s = 0, ts = 0;
        #pragma unroll
        for (int e = 0; e < NE; e++) {
            g_off[e] = s;
            g_tile_start[e] = ts;
            s  += g_cnt[e];
            ts += (g_cnt[e] + TM - 1) / TM;
        }
        g_off[NE] = s;
        g_tile_start[NE] = ts;
    }
}

// ---------------- 3) scatter ----------------
__global__ void scatter_kernel() {
    int t = blockIdx.x * blockDim.x + threadIdx.x;
    if (t >= N_TOK) return;
    int e = g_gate_idx[t];
    int pos = atomicAdd(&g_cur[e], 1);
    g_perm[g_off[e] + pos] = t;
}

// ---------------- 4/5) split-bf16 grouped GEMM via mma.sync ----------------
// 128x256 CTA tile, 16 warps (2x8), warp tile 64x32, 2-stage cp.async pipeline.
// FIRST:  H(hi/lo) = relu(X[perm] @ W1^T + b1)    KDIM=512,  NOUT=1024
// !FIRST: out[tok] = gate * (H @ W2^T + b2)       KDIM=1024, NOUT=512
template <int KDIM, int NOUT, bool FIRST>
__global__ __launch_bounds__(NTHREADS, 1) void moe_gemm(const float* __restrict__ BIAS,
                                                        float* __restrict__ OUT)
{
    extern __shared__ char smem[];
    constexpr int NC = KDIM / KC;

    int bt = blockIdx.x;
    if (bt >= g_tile_start[NE]) return;
    int e = 0;
    while (bt >= g_tile_start[e + 1]) e++;
    int m0  = (bt - g_tile_start[e]) * TM;
    int cnt = g_cnt[e];
    int off = g_off[e];
    int n0  = blockIdx.y * TN;

    uint32_t sb = smem_u32(smem);
    int tid = threadIdx.x, wid = tid >> 5, lane = tid & 31;

    if (tid < TM) {
        int am = m0 + tid;
        bool v = am < cnt;
        int tok = v ? g_perm[off + am] : 0;
        long rowb;
        if (FIRST) rowb = (long)tok * (KDIM * 2);
        else       rowb = (long)(off + (v ? am : 0)) * (KDIM * 2);
        ((long*)(smem + SM_ABASE))[tid] = rowb;
        ((int*)(smem + SM_TOK))[tid] = tok;
    }
    if (tid < TN) ((float*)(smem + SM_BIAS))[tid] = BIAS[e * NOUT + n0 + tid];

    const char* Ah = FIRST ? (const char*)g_xhi  : (const char*)g_hhi;
    const char* Al = FIRST ? (const char*)g_xlo  : (const char*)g_hlo;
    const char* Bh = (FIRST ? (const char*)g_w1hi : (const char*)g_w2hi)
                     + ((size_t)(e * NOUT + n0)) * (KDIM * 2);
    const char* Bl = (FIRST ? (const char*)g_w1lo : (const char*)g_w2lo)
                     + ((size_t)(e * NOUT + n0)) * (KDIM * 2);
    const long* s_abase = (const long*)(smem + SM_ABASE);

    __syncthreads();   // abase table ready

    int lr = tid >> 3, lseg = tid & 7;   // 64 rows x 8 segs per pass of 512 threads
    auto load_chunk = [&](int c, int s) {
        long k0b = (long)c * (KC * 2);
        uint32_t base = sb + s * STAGE_BYTES;
        #pragma unroll
        for (int i = 0; i < 2; i++) {                 // A: 128 rows, both planes
            int r = lr + i * 64;
            uint32_t d = swz(r * 128 + lseg * 16);
            long ro = s_abase[r] + k0b + lseg * 16;
            cp_async16(base + d,         Ah + ro);
            cp_async16(base + 16384 + d, Al + ro);
        }
        #pragma unroll
        for (int i = 0; i < 4; i++) {                 // B: 256 rows, both planes
            int r = lr + i * 64;
            uint32_t d = swz(r * 128 + lseg * 16);
            long rb = (long)r * (KDIM * 2) + k0b + lseg * 16;
            cp_async16(base + 32768 + d, Bh + rb);
            cp_async16(base + 65536 + d, Bl + rb);
        }
    };

    load_chunk(0, 0); CP_COMMIT();
    load_chunk(1, 1); CP_COMMIT();

    // warp layout: 2 (M) x 8 (N); warp tile 64x32
    int wm = (wid >> 3) * 64;
    int wn = (wid & 7) * 32;
    int a_row = lane & 15;
    uint32_t a_col = (lane >> 4) * 16;                  // byte
    int b_row = wn + ((lane >> 4) << 3) + (lane & 7);   // + p*16
    uint32_t b_col = ((lane >> 3) & 1) * 16;

    float acc[4][4][4];
    #pragma unroll
    for (int i = 0; i < 4; i++)
        #pragma unroll
        for (int j = 0; j < 4; j++)
            #pragma unroll
            for (int k = 0; k < 4; k++) acc[i][j][k] = 0.f;

    for (int c = 0; c < NC; c++) {
        int s = c & 1;
        CP_WAIT1();
        __syncthreads();
        uint32_t ahb = sb + s * STAGE_BYTES;
        uint32_t alb = ahb + 16384;
        uint32_t bhb = ahb + 32768;
        uint32_t blb = ahb + 65536;

        #pragma unroll
        for (int ks = 0; ks < 4; ks++) {
            uint32_t kb = ks * 32;   // 16 elems * 2B
            uint32_t ah[4][4], al[4][4], b[4][2];
            #pragma unroll
            for (int f = 0; f < 4; f++)
                ldsm4(ah[f], ahb + swz((wm + f * 16 + a_row) * 128 + kb + a_col));
            #pragma unroll
            for (int f = 0; f < 4; f++)
                ldsm4(al[f], alb + swz((wm + f * 16 + a_row) * 128 + kb + a_col));
            #pragma unroll
            for (int p = 0; p < 2; p++) {
                uint32_t r[4];
                ldsm4(r, bhb + swz((b_row + p * 16) * 128 + kb + b_col));
                b[2 * p][0] = r[0]; b[2 * p][1] = r[1];
                b[2 * p + 1][0] = r[2]; b[2 * p + 1][1] = r[3];
            }
            #pragma unroll
            for (int f = 0; f < 4; f++)
                #pragma unroll
                for (int g = 0; g < 4; g++)
                    mma16816(acc[f][g], ah[f], b[g]);   // hi*hi
            #pragma unroll
            for (int f = 0; f < 4; f++)
                #pragma unroll
                for (int g = 0; g < 4; g++)
                    mma16816(acc[f][g], al[f], b[g]);   // lo*hi
            #pragma unroll
            for (int p = 0; p < 2; p++) {               // overwrite b with B-lo
                uint32_t r[4];
                ldsm4(r, blb + swz((b_row + p * 16) * 128 + kb + b_col));
                b[2 * p][0] = r[0]; b[2 * p][1] = r[1];
                b[2 * p + 1][0] = r[2]; b[2 * p + 1][1] = r[3];
            }
            #pragma unroll
            for (int f = 0; f < 4; f++)
                #pragma unroll
                for (int g = 0; g < 4; g++)
                    mma16816(acc[f][g], ah[f], b[g]);   // hi*lo
        }
        __syncthreads();
        if (c + STAGES < NC) load_chunk(c + STAGES, s);
        CP_COMMIT();
    }
    CP_WAIT0();

    // ---- epilogue ----
    // acc[f][g][k]: row = wm + f*16 + (k>=2)*8 + lane/4 ; col = wn + g*8 + 2*(lane%4) + (k&1)
    const float* sbias = (const float*)(smem + SM_BIAS);
    const int* s_tok = (const int*)(smem + SM_TOK);
    int rbase = wm + (lane >> 2);
    int cbase = wn + 2 * (lane & 3);

    #pragma unroll
    for (int f = 0; f < 4; f++) {
        #pragma unroll
        for (int half = 0; half < 2; half++) {
            int lrow = rbase + f * 16 + half * 8;
            if (m0 + lrow >= cnt) continue;
            if (FIRST) {
                size_t hrow = (size_t)(off + m0 + lrow) * H_DIM + n0;
                #pragma unroll
                for (int g = 0; g < 4; g++) {
                    int col = cbase + g * 8;
                    float v0 = fmaxf(acc[f][g][2 * half]     + sbias[col],     0.f);
                    float v1 = fmaxf(acc[f][g][2 * half + 1] + sbias[col + 1], 0.f);
                    __nv_bfloat16 h0 = __float2bfloat16_rn(v0);
                    __nv_bfloat16 h1 = __float2bfloat16_rn(v1);
                    *(__nv_bfloat162*)(g_hhi + hrow + col) = __halves2bfloat162(h0, h1);
                    *(__nv_bfloat162*)(g_hlo + hrow + col) = __halves2bfloat162(
                        __float2bfloat16_rn(v0 - __bfloat162float(h0)),
                        __float2bfloat16_rn(v1 - __bfloat162float(h1)));
                }
            } else {
                int tok = s_tok[lrow];
                float gv = g_gate_val[tok];
                float* orow = OUT + (size_t)tok * D_IN + n0;
                #pragma unroll
                for (int g = 0; g < 4; g++) {
                    int col = cbase + g * 8;
                    float2 o;
                    o.x = (acc[f][g][2 * half]     + sbias[col])     * gv;
                    o.y = (acc[f][g][2 * half + 1] + sbias[col + 1]) * gv;
                    *(float2*)(orow + col) = o;
                }
            }
        }
    }
}

// ---------------- launch ----------------
extern "C" void kernel_launch(void* const* d_in, const int* in_sizes, int n_in,
                              void* d_out, int out_size)
{
    const float* x   = (const float*)d_in[0];
    const float* emb = (const float*)d_in[1];
    const float* rw  = (const float*)d_in[2];
    const float* w1  = (const float*)d_in[3];
    const float* b1  = (const float*)d_in[4];
    const float* w2  = (const float*)d_in[5];
    const float* b2  = (const float*)d_in[6];
    float* out = (float*)d_out;

    cudaFuncSetAttribute(moe_gemm<D_IN, H_DIM, true>,
                         cudaFuncAttributeMaxDynamicSharedMemorySize, SMEM_DYN);
    cudaFuncSetAttribute(moe_gemm<H_DIM, D_IN, false>,
                         cudaFuncAttributeMaxDynamicSharedMemorySize, SMEM_DYN);

    zero_kernel<<<1, 32>>>();
    split_kernel<0><<<1024, 256>>>((const float4*)x,  N_TOK * D_IN / 4);
    split_kernel<1><<<512, 256>>>((const float4*)w1, NE * H_DIM * D_IN / 4);
    split_kernel<2><<<512, 256>>>((const float4*)w2, NE * D_IN * H_DIM / 4);
    router_kernel<<<RBLK, 256>>>(x, emb, rw);
    finalize_kernel<<<1, 256>>>(out, out_size);
    scatter_kernel<<<N_TOK / 256, 256>>>();
    moe_gemm<D_IN, H_DIM, true><<<dim3(MAX_TILES, H_DIM / TN), NTHREADS, SMEM_DYN>>>(b1, nullptr);
    moe_gemm<H_DIM, D_IN, false><<<dim3(MAX_TILES, D_IN / TN), NTHREADS, SMEM_DYN>>>(b2, out);
}

// round 7
// speedup vs baseline: 6.0670x; 1.9999x over previous
#include <cuda_runtime.h>
#include <cuda_fp16.h>
#include <cstdint>

// ---------------- Problem constants ----------------
#define N_TOK (16 * 2048)   // 32768 tokens
#define D_IN  512
#define E_DIM 256
#define H_DIM 1024
#define NE    4
#define RIN   (E_DIM + D_IN)
#define EPSV  1e-10f

// ---------------- GEMM tiling ----------------
#define TM 128
#define TN 256
#define KC 64                         // K elements per chunk (64 fp16 = 128B/row)
#define STAGES 3
#define NTHREADS 512
#define MAX_TILES (N_TOK / TM + NE)   // 260 worst-case M-tiles

#define RTOK_PER_BLK 8
#define RBLK (N_TOK / RTOK_PER_BLK)

// ---------------- Shared memory layout ----------------
// Per stage: A 16K | B 32K = 48K
#define STAGE_BYTES 49152
#define SM_BIAS  (STAGES * STAGE_BYTES)          // 147456: 256 floats
#define SM_ABASE (SM_BIAS + 1024)                // 128 x int64 row byte offsets
#define SM_TOK   (SM_ABASE + 1024)               // 128 x int
#define SMEM_DYN (SM_TOK + 512)

// ---------------- Device scratch ----------------
__device__ int   g_gate_idx[N_TOK];
__device__ float g_gate_val[N_TOK];
__device__ int   g_perm[N_TOK + 128];
__device__ int   g_cnt[NE];
__device__ int   g_cur[NE];
__device__ int   g_off[NE + 1];
__device__ int   g_tile_start[NE + 1];
__device__ float g_part_l1[RBLK];
__device__ float g_part_imp[RBLK * NE];

__device__ __half g_xh[(size_t)N_TOK * D_IN];
__device__ __half g_w1h[(size_t)NE * H_DIM * D_IN];
__device__ __half g_w2h[(size_t)NE * D_IN * H_DIM];
__device__ __half g_hh[(size_t)(N_TOK + 128) * H_DIM];

// ---------------- PTX helpers (baseline ISA only) ----------------
__device__ __forceinline__ uint32_t smem_u32(const void* p) {
    uint32_t a;
    asm("{ .reg .u64 t; cvta.to.shared.u64 t, %1; cvt.u32.u64 %0, t; }" : "=r"(a) : "l"(p));
    return a;
}
__device__ __forceinline__ void cp_async16(uint32_t dst, const void* src) {
    asm volatile("cp.async.cg.shared.global [%0], [%1], 16;" :: "r"(dst), "l"(src) : "memory");
}
#define CP_COMMIT() asm volatile("cp.async.commit_group;" ::: "memory")
#define CP_WAIT2()  asm volatile("cp.async.wait_group 2;" ::: "memory")
#define CP_WAIT0()  asm volatile("cp.async.wait_group 0;" ::: "memory")

__device__ __forceinline__ void ldsm4(uint32_t* r, uint32_t addr) {
    asm volatile("ldmatrix.sync.aligned.m8n8.x4.shared.b16 {%0,%1,%2,%3}, [%4];"
        : "=r"(r[0]), "=r"(r[1]), "=r"(r[2]), "=r"(r[3]) : "r"(addr));
}
__device__ __forceinline__ void mma16816(float* c, const uint32_t* a, const uint32_t* b) {
    asm volatile(
        "mma.sync.aligned.m16n8k16.row.col.f32.f16.f16.f32 "
        "{%0,%1,%2,%3}, {%4,%5,%6,%7}, {%8,%9}, {%0,%1,%2,%3};"
        : "+f"(c[0]), "+f"(c[1]), "+f"(c[2]), "+f"(c[3])
        : "r"(a[0]), "r"(a[1]), "r"(a[2]), "r"(a[3]), "r"(b[0]), "r"(b[1]));
}
__device__ __forceinline__ uint32_t swz(uint32_t b) { return b ^ ((b >> 3) & 0x70); }

// ---------------- 0) reset per-call state ----------------
__global__ void zero_kernel() {
    int t = threadIdx.x;
    if (t < NE) { g_cnt[t] = 0; g_cur[t] = 0; }
}

// ---------------- convert f32 -> fp16 plane ----------------
template <int SEL>
__global__ __launch_bounds__(256) void half_kernel(const float4* __restrict__ src, int n4) {
    __half2* h2;
    if (SEL == 0)      h2 = (__half2*)g_xh;
    else if (SEL == 1) h2 = (__half2*)g_w1h;
    else               h2 = (__half2*)g_w2h;
    int stride = gridDim.x * blockDim.x;
    for (int i = blockIdx.x * blockDim.x + threadIdx.x; i < n4; i += stride) {
        float4 v = src[i];
        h2[2 * i]     = __floats2half2_rn(v.x, v.y);
        h2[2 * i + 1] = __floats2half2_rn(v.z, v.w);
    }
}

// ---------------- 1) router ----------------
__global__ __launch_bounds__(256) void router_kernel(
    const float* __restrict__ x, const float* __restrict__ emb,
    const float* __restrict__ rw)
{
    __shared__ float s_rw[RIN * NE];
    __shared__ float s_l1[RTOK_PER_BLK];
    __shared__ float s_imp[RTOK_PER_BLK][NE];

    int t = threadIdx.x;
    for (int i = t; i < RIN * NE; i += blockDim.x) s_rw[i] = rw[i];
    __syncthreads();

    int warp = t >> 5, lane = t & 31;
    int tok = blockIdx.x * RTOK_PER_BLK + warp;

    float acc0 = 0.f, acc1 = 0.f, acc2 = 0.f, acc3 = 0.f;
    const float* er = emb + (size_t)tok * E_DIM;
    const float* xr = x   + (size_t)tok * D_IN;

    #pragma unroll 4
    for (int k = lane; k < E_DIM; k += 32) {
        float v = er[k];
        const float* w = s_rw + k * NE;
        acc0 += v * w[0]; acc1 += v * w[1]; acc2 += v * w[2]; acc3 += v * w[3];
    }
    #pragma unroll 4
    for (int k = lane; k < D_IN; k += 32) {
        float v = xr[k];
        const float* w = s_rw + (E_DIM + k) * NE;
        acc0 += v * w[0]; acc1 += v * w[1]; acc2 += v * w[2]; acc3 += v * w[3];
    }
    #pragma unroll
    for (int o = 16; o; o >>= 1) {
        acc0 += __shfl_xor_sync(0xFFFFFFFFu, acc0, o);
        acc1 += __shfl_xor_sync(0xFFFFFFFFu, acc1, o);
        acc2 += __shfl_xor_sync(0xFFFFFFFFu, acc2, o);
        acc3 += __shfl_xor_sync(0xFFFFFFFFu, acc3, o);
    }

    if (lane == 0) {
        float lg[NE] = {acc0, acc1, acc2, acc3};
        float m = lg[0];
        #pragma unroll
        for (int e = 1; e < NE; e++) m = fmaxf(m, lg[e]);
        float p[NE], s = 0.f;
        #pragma unroll
        for (int e = 0; e < NE; e++) { p[e] = __expf(lg[e] - m); s += p[e]; }
        float inv = 1.f / s;
        float sump = 0.f, sq = 0.f;
        float best = -1.f; int bi = 0;
        #pragma unroll
        for (int e = 0; e < NE; e++) {
            p[e] *= inv;
            sump += p[e];
            sq   += p[e] * p[e];
            if (p[e] > best) { best = p[e]; bi = e; }
        }
        g_gate_idx[tok] = bi;
        g_gate_val[tok] = best;
        atomicAdd(&g_cnt[bi], 1);
        s_l1[warp] = sump / (sqrtf(sq) + EPSV);
        #pragma unroll
        for (int e = 0; e < NE; e++) s_imp[warp][e] = p[e];
    }
    __syncthreads();
    if (t == 0) {
        float a = 0.f;
        #pragma unroll
        for (int w = 0; w < RTOK_PER_BLK; w++) a += s_l1[w];
        g_part_l1[blockIdx.x] = a;
    }
    if (t < NE) {
        float a = 0.f;
        #pragma unroll
        for (int w = 0; w < RTOK_PER_BLK; w++) a += s_imp[w][t];
        g_part_imp[blockIdx.x * NE + t] = a;
    }
}

// ---------------- 2) finalize ----------------
__global__ void finalize_kernel(float* __restrict__ out, int out_size) {
    __shared__ float sh[256];
    int t = threadIdx.x;
    float v[5] = {0.f, 0.f, 0.f, 0.f, 0.f};
    for (int b = t; b < RBLK; b += 256) {
        v[0] += g_part_l1[b];
        #pragma unroll
        for (int e = 0; e < NE; e++) v[1 + e] += g_part_imp[b * NE + e];
    }
    float res[5];
    #pragma unroll
    for (int q = 0; q < 5; q++) {
        sh[t] = v[q]; __syncthreads();
        for (int s = 128; s; s >>= 1) {
            if (t < s) sh[t] += sh[t + s];
            __syncthreads();
        }
        res[q] = sh[0];
        __syncthreads();
    }
    if (t == 0) {
        float l1 = res[0] / (float)N_TOK;
        float mean = (res[1] + res[2] + res[3] + res[4]) * 0.25f;
        float var = 0.f;
        #pragma unroll
        for (int e = 0; e < NE; e++) {
            float d = res[1 + e] - mean;
            var += d * d;
        }
        var *= 0.25f;
        float imp = var / (mean * mean + EPSV);
        if (out_size >= N_TOK * D_IN + 2) {
            out[N_TOK * D_IN]     = l1;
            out[N_TOK * D_IN + 1] = imp;
        }
        int s = 0, ts = 0;
        #pragma unroll
        for (int e = 0; e < NE; e++) {
            g_off[e] = s;
            g_tile_start[e] = ts;
            s  += g_cnt[e];
            ts += (g_cnt[e] + TM - 1) / TM;
        }
        g_off[NE] = s;
        g_tile_start[NE] = ts;
    }
}

// ---------------- 3) scatter ----------------
__global__ void scatter_kernel() {
    int t = blockIdx.x * blockDim.x + threadIdx.x;
    if (t >= N_TOK) return;
    int e = g_gate_idx[t];
    int pos = atomicAdd(&g_cur[e], 1);
    g_perm[g_off[e] + pos] = t;
}

// ---------------- 4/5) fp16 grouped GEMM via mma.sync ----------------
// 128x256 CTA tile, 16 warps (2x8), warp tile 64x32, 3-stage cp.async pipeline.
// FIRST:  H = relu(X[perm] @ W1^T + b1)  (fp16 out)   KDIM=512,  NOUT=1024
// !FIRST: out[tok] = gate * (H @ W2^T + b2)  (f32)    KDIM=1024, NOUT=512
template <int KDIM, int NOUT, bool FIRST>
__global__ __launch_bounds__(NTHREADS, 1) void moe_gemm(const float* __restrict__ BIAS,
                                                        float* __restrict__ OUT)
{
    extern __shared__ char smem[];
    constexpr int NC = KDIM / KC;

    int bt = blockIdx.x;
    if (bt >= g_tile_start[NE]) return;
    int e = 0;
    while (bt >= g_tile_start[e + 1]) e++;
    int m0  = (bt - g_tile_start[e]) * TM;
    int cnt = g_cnt[e];
    int off = g_off[e];
    int n0  = blockIdx.y * TN;

    uint32_t sb = smem_u32(smem);
    int tid = threadIdx.x, wid = tid >> 5, lane = tid & 31;

    if (tid < TM) {
        int am = m0 + tid;
        bool v = am < cnt;
        int tok = v ? g_perm[off + am] : 0;
        long rowb;
        if (FIRST) rowb = (long)tok * (KDIM * 2);
        else       rowb = (long)(off + (v ? am : 0)) * (KDIM * 2);
        ((long*)(smem + SM_ABASE))[tid] = rowb;
        ((int*)(smem + SM_TOK))[tid] = tok;
    }
    if (tid < TN) ((float*)(smem + SM_BIAS))[tid] = BIAS[e * NOUT + n0 + tid];

    const char* A = FIRST ? (const char*)g_xh : (const char*)g_hh;
    const char* B = (FIRST ? (const char*)g_w1h : (const char*)g_w2h)
                    + ((size_t)(e * NOUT + n0)) * (KDIM * 2);
    const long* s_abase = (const long*)(smem + SM_ABASE);

    __syncthreads();   // abase table ready

    int lr = tid >> 3, lseg = tid & 7;   // 64 rows x 8 segs per pass of 512 threads
    auto load_chunk = [&](int c, int s) {
        long k0b = (long)c * (KC * 2);
        uint32_t base = sb + s * STAGE_BYTES;
        #pragma unroll
        for (int i = 0; i < 2; i++) {                 // A: 128 rows
            int r = lr + i * 64;
            uint32_t d = swz(r * 128 + lseg * 16);
            cp_async16(base + d, A + s_abase[r] + k0b + lseg * 16);
        }
        #pragma unroll
        for (int i = 0; i < 4; i++) {                 // B: 256 rows
            int r = lr + i * 64;
            uint32_t d = swz(r * 128 + lseg * 16);
            cp_async16(base + 16384 + d, B + (long)r * (KDIM * 2) + k0b + lseg * 16);
        }
    };

    load_chunk(0, 0); CP_COMMIT();
    load_chunk(1, 1); CP_COMMIT();
    load_chunk(2, 2); CP_COMMIT();

    // warp layout: 2 (M) x 8 (N); warp tile 64x32
    int wm = (wid >> 3) * 64;
    int wn = (wid & 7) * 32;
    int a_row = lane & 15;
    uint32_t a_col = (lane >> 4) * 16;                  // byte
    int b_row = wn + ((lane >> 4) << 3) + (lane & 7);   // + p*16
    uint32_t b_col = ((lane >> 3) & 1) * 16;

    float acc[4][4][4];
    #pragma unroll
    for (int i = 0; i < 4; i++)
        #pragma unroll
        for (int j = 0; j < 4; j++)
            #pragma unroll
            for (int k = 0; k < 4; k++) acc[i][j][k] = 0.f;

    for (int c = 0; c < NC; c++) {
        int s = c % STAGES;
        CP_WAIT2();
        __syncthreads();
        uint32_t ab = sb + s * STAGE_BYTES;
        uint32_t bb = ab + 16384;

        #pragma unroll
        for (int ks = 0; ks < 4; ks++) {
            uint32_t kb = ks * 32;   // 16 elems * 2B
            uint32_t a[4][4], b[4][2];
            #pragma unroll
            for (int f = 0; f < 4; f++)
                ldsm4(a[f], ab + swz((wm + f * 16 + a_row) * 128 + kb + a_col));
            #pragma unroll
            for (int p = 0; p < 2; p++) {
                uint32_t r[4];
                ldsm4(r, bb + swz((b_row + p * 16) * 128 + kb + b_col));
                b[2 * p][0] = r[0]; b[2 * p][1] = r[1];
                b[2 * p + 1][0] = r[2]; b[2 * p + 1][1] = r[3];
            }
            #pragma unroll
            for (int f = 0; f < 4; f++)
                #pragma unroll
                for (int g = 0; g < 4; g++)
                    mma16816(acc[f][g], a[f], b[g]);
        }
        __syncthreads();
        if (c + STAGES < NC) load_chunk(c + STAGES, s);
        CP_COMMIT();
    }
    CP_WAIT0();

    // ---- epilogue ----
    // acc[f][g][k]: row = wm + f*16 + (k>=2)*8 + lane/4 ; col = wn + g*8 + 2*(lane%4) + (k&1)
    const float* sbias = (const float*)(smem + SM_BIAS);
    const int* s_tok = (const int*)(smem + SM_TOK);
    int rbase = wm + (lane >> 2);
    int cbase = wn + 2 * (lane & 3);

    #pragma unroll
    for (int f = 0; f < 4; f++) {
        #pragma unroll
        for (int half = 0; half < 2; half++) {
            int lrow = rbase + f * 16 + half * 8;
            if (m0 + lrow >= cnt) continue;
            if (FIRST) {
                size_t hrow = (size_t)(off + m0 + lrow) * H_DIM + n0;
                #pragma unroll
                for (int g = 0; g < 4; g++) {
                    int col = cbase + g * 8;
                    float v0 = fmaxf(acc[f][g][2 * half]     + sbias[col],     0.f);
                    float v1 = fmaxf(acc[f][g][2 * half + 1] + sbias[col + 1], 0.f);
                    *(__half2*)(g_hh + hrow + col) = __floats2half2_rn(v0, v1);
                }
            } else {
                int tok = s_tok[lrow];
                float gv = g_gate_val[tok];
                float* orow = OUT + (size_t)tok * D_IN + n0;
                #pragma unroll
                for (int g = 0; g < 4; g++) {
                    int col = cbase + g * 8;
                    float2 o;
                    o.x = (acc[f][g][2 * half]     + sbias[col])     * gv;
                    o.y = (acc[f][g][2 * half + 1] + sbias[col + 1]) * gv;
                    *(float2*)(orow + col) = o;
                }
            }
        }
    }
}

// ---------------- launch ----------------
extern "C" void kernel_launch(void* const* d_in, const int* in_sizes, int n_in,
                              void* d_out, int out_size)
{
    const float* x   = (const float*)d_in[0];
    const float* emb = (const float*)d_in[1];
    const float* rw  = (const float*)d_in[2];
    const float* w1  = (const float*)d_in[3];
    const float* b1  = (const float*)d_in[4];
    const float* w2  = (const float*)d_in[5];
    const float* b2  = (const float*)d_in[6];
    float* out = (float*)d_out;

    cudaFuncSetAttribute(moe_gemm<D_IN, H_DIM, true>,
                         cudaFuncAttributeMaxDynamicSharedMemorySize, SMEM_DYN);
    cudaFuncSetAttribute(moe_gemm<H_DIM, D_IN, false>,
                         cudaFuncAttributeMaxDynamicSharedMemorySize, SMEM_DYN);

    zero_kernel<<<1, 32>>>();
    half_kernel<0><<<1024, 256>>>((const float4*)x,  N_TOK * D_IN / 4);
    half_kernel<1><<<512, 256>>>((const float4*)w1, NE * H_DIM * D_IN / 4);
    half_kernel<2><<<512, 256>>>((const float4*)w2, NE * D_IN * H_DIM / 4);
    router_kernel<<<RBLK, 256>>>(x, emb, rw);
    finalize_kernel<<<1, 256>>>(out, out_size);
    scatter_kernel<<<N_TOK / 256, 256>>>();
    moe_gemm<D_IN, H_DIM, true><<<dim3(MAX_TILES, H_DIM / TN), NTHREADS, SMEM_DYN>>>(b1, nullptr);
    moe_gemm<H_DIM, D_IN, false><<<dim3(MAX_TILES, D_IN / TN), NTHREADS, SMEM_DYN>>>(b2, out);
}

// round 10
// speedup vs baseline: 6.3375x; 1.0446x over previous
#include <cuda_runtime.h>
#include <cuda_fp16.h>
#include <cstdint>

// ---------------- Problem constants ----------------
#define N_TOK (16 * 2048)   // 32768 tokens
#define D_IN  512
#define E_DIM 256
#define H_DIM 1024
#define NE    4
#define RIN   (E_DIM + D_IN)
#define EPSV  1e-10f

// ---------------- GEMM tiling ----------------
#define TM 128
#define TN 256
#define KC 64                         // K elements per chunk (64 fp16 = 128B/row)
#define STAGES 4
#define NTHREADS 512
#define MAX_TILES (N_TOK / TM + NE)   // 260 worst-case M-tiles

#define RTOK_PER_BLK 8
#define RBLK (N_TOK / RTOK_PER_BLK)

// ---------------- Shared memory layout ----------------
// Per stage: A 16K | B 32K = 48K
#define STAGE_BYTES 49152
#define SM_BIAS  (STAGES * STAGE_BYTES)          // 196608: 256 floats
#define SM_ABASE (SM_BIAS + 1024)                // 128 x int64 row byte offsets
#define SM_TOK   (SM_ABASE + 1024)               // 128 x int
#define SMEM_DYN (SM_TOK + 512)                  // ~199168 bytes

// ---------------- Device scratch ----------------
__device__ int   g_gate_idx[N_TOK];
__device__ float g_gate_val[N_TOK];
__device__ int   g_perm[N_TOK + 128];
__device__ int   g_cnt[NE];
__device__ int   g_cur[NE];
__device__ int   g_off[NE + 1];
__device__ int   g_tile_start[NE + 1];
__device__ float g_part_l1[RBLK];
__device__ float g_part_imp[RBLK * NE];

__device__ __half g_xh[(size_t)N_TOK * D_IN];
__device__ __half g_w1h[(size_t)NE * H_DIM * D_IN];
__device__ __half g_w2h[(size_t)NE * D_IN * H_DIM];
__device__ __half g_hh[(size_t)(N_TOK + 128) * H_DIM];

// ---------------- PTX helpers (baseline ISA only) ----------------
__device__ __forceinline__ uint32_t smem_u32(const void* p) {
    uint32_t a;
    asm("{ .reg .u64 t; cvta.to.shared.u64 t, %1; cvt.u32.u64 %0, t; }" : "=r"(a) : "l"(p));
    return a;
}
__device__ __forceinline__ void cp_async16(uint32_t dst, const void* src) {
    asm volatile("cp.async.cg.shared.global [%0], [%1], 16;" :: "r"(dst), "l"(src) : "memory");
}
#define CP_COMMIT() asm volatile("cp.async.commit_group;" ::: "memory")
// Wait until at most STAGES-1 groups pending => oldest (current chunk) is resident.
#define CP_WAITP()  asm volatile("cp.async.wait_group 3;" ::: "memory")
#define CP_WAIT0()  asm volatile("cp.async.wait_group 0;" ::: "memory")

__device__ __forceinline__ void ldsm4(uint32_t* r, uint32_t addr) {
    asm volatile("ldmatrix.sync.aligned.m8n8.x4.shared.b16 {%0,%1,%2,%3}, [%4];"
        : "=r"(r[0]), "=r"(r[1]), "=r"(r[2]), "=r"(r[3]) : "r"(addr));
}
__device__ __forceinline__ void mma16816(float* c, const uint32_t* a, const uint32_t* b) {
    asm volatile(
        "mma.sync.aligned.m16n8k16.row.col.f32.f16.f16.f32 "
        "{%0,%1,%2,%3}, {%4,%5,%6,%7}, {%8,%9}, {%0,%1,%2,%3};"
        : "+f"(c[0]), "+f"(c[1]), "+f"(c[2]), "+f"(c[3])
        : "r"(a[0]), "r"(a[1]), "r"(a[2]), "r"(a[3]), "r"(b[0]), "r"(b[1]));
}
__device__ __forceinline__ uint32_t swz(uint32_t b) { return b ^ ((b >> 3) & 0x70); }

// ---------------- 0) reset per-call state ----------------
__global__ void zero_kernel() {
    int t = threadIdx.x;
    if (t < NE) { g_cnt[t] = 0; g_cur[t] = 0; }
}

// ---------------- convert f32 -> fp16 plane (weights only; x fused into router) ----
template <int SEL>
__global__ __launch_bounds__(256) void half_kernel(const float4* __restrict__ src, int n4) {
    __half2* h2;
    if (SEL == 1) h2 = (__half2*)g_w1h;
    else          h2 = (__half2*)g_w2h;
    int stride = gridDim.x * blockDim.x;
    for (int i = blockIdx.x * blockDim.x + threadIdx.x; i < n4; i += stride) {
        float4 v = src[i];
        h2[2 * i]     = __floats2half2_rn(v.x, v.y);
        h2[2 * i + 1] = __floats2half2_rn(v.z, v.w);
    }
}

// ---------------- 1) router (+ fused x -> fp16 conversion) ----------------
__global__ __launch_bounds__(256) void router_kernel(
    const float* __restrict__ x, const float* __restrict__ emb,
    const float* __restrict__ rw)
{
    __shared__ float s_rw[RIN * NE];
    __shared__ float s_l1[RTOK_PER_BLK];
    __shared__ float s_imp[RTOK_PER_BLK][NE];

    int t = threadIdx.x;
    for (int i = t; i < RIN * NE; i += blockDim.x) s_rw[i] = rw[i];
    __syncthreads();

    int warp = t >> 5, lane = t & 31;
    int tok = blockIdx.x * RTOK_PER_BLK + warp;

    float acc0 = 0.f, acc1 = 0.f, acc2 = 0.f, acc3 = 0.f;
    const float* er = emb + (size_t)tok * E_DIM;
    const float* xr = x   + (size_t)tok * D_IN;

    #pragma unroll 4
    for (int k = lane; k < E_DIM; k += 32) {
        float v = er[k];
        const float* w = s_rw + k * NE;
        acc0 += v * w[0]; acc1 += v * w[1]; acc2 += v * w[2]; acc3 += v * w[3];
    }
    #pragma unroll 4
    for (int k = lane; k < D_IN; k += 32) {
        float v = xr[k];
        const float* w = s_rw + (E_DIM + k) * NE;
        acc0 += v * w[0]; acc1 += v * w[1]; acc2 += v * w[2]; acc3 += v * w[3];
    }

    // fused x -> fp16 (rows are hot in L1/L2 from the loop above)
    {
        const float4* xr4 = (const float4*)xr;
        __half2* xh2 = (__half2*)(g_xh + (size_t)tok * D_IN);
        #pragma unroll
        for (int i = 0; i < 4; i++) {
            float4 v = xr4[lane + 32 * i];
            xh2[2 * (lane + 32 * i)]     = __floats2half2_rn(v.x, v.y);
            xh2[2 * (lane + 32 * i) + 1] = __floats2half2_rn(v.z, v.w);
        }
    }

    #pragma unroll
    for (int o = 16; o; o >>= 1) {
        acc0 += __shfl_xor_sync(0xFFFFFFFFu, acc0, o);
        acc1 += __shfl_xor_sync(0xFFFFFFFFu, acc1, o);
        acc2 += __shfl_xor_sync(0xFFFFFFFFu, acc2, o);
        acc3 += __shfl_xor_sync(0xFFFFFFFFu, acc3, o);
    }

    if (lane == 0) {
        float lg[NE] = {acc0, acc1, acc2, acc3};
        float m = lg[0];
        #pragma unroll
        for (int e = 1; e < NE; e++) m = fmaxf(m, lg[e]);
        float p[NE], s = 0.f;
        #pragma unroll
        for (int e = 0; e < NE; e++) { p[e] = __expf(lg[e] - m); s += p[e]; }
        float inv = 1.f / s;
        float sump = 0.f, sq = 0.f;
        float best = -1.f; int bi = 0;
        #pragma unroll
        for (int e = 0; e < NE; e++) {
            p[e] *= inv;
            sump += p[e];
            sq   += p[e] * p[e];
            if (p[e] > best) { best = p[e]; bi = e; }
        }
        g_gate_idx[tok] = bi;
        g_gate_val[tok] = best;
        atomicAdd(&g_cnt[bi], 1);
        s_l1[warp] = sump / (sqrtf(sq) + EPSV);
        #pragma unroll
        for (int e = 0; e < NE; e++) s_imp[warp][e] = p[e];
    }
    __syncthreads();
    if (t == 0) {
        float a = 0.f;
        #pragma unroll
        for (int w = 0; w < RTOK_PER_BLK; w++) a += s_l1[w];
        g_part_l1[blockIdx.x] = a;
    }
    if (t < NE) {
        float a = 0.f;
        #pragma unroll
        for (int w = 0; w < RTOK_PER_BLK; w++) a += s_imp[w][t];
        g_part_imp[blockIdx.x * NE + t] = a;
    }
}

// ---------------- 2) finalize ----------------
__global__ void finalize_kernel(float* __restrict__ out, int out_size) {
    __shared__ float sh[256];
    int t = threadIdx.x;
    float v[5] = {0.f, 0.f, 0.f, 0.f, 0.f};
    for (int b = t; b < RBLK; b += 256) {
        v[0] += g_part_l1[b];
        #pragma unroll
        for (int e = 0; e < NE; e++) v[1 + e] += g_part_imp[b * NE + e];
    }
    float res[5];
    #pragma unroll
    for (int q = 0; q < 5; q++) {
        sh[t] = v[q]; __syncthreads();
        for (int s = 128; s; s >>= 1) {
            if (t < s) sh[t] += sh[t + s];
            __syncthreads();
        }
        res[q] = sh[0];
        __syncthreads();
    }
    if (t == 0) {
        float l1 = res[0] / (float)N_TOK;
        float mean = (res[1] + res[2] + res[3] + res[4]) * 0.25f;
        float var = 0.f;
        #pragma unroll
        for (int e = 0; e < NE; e++) {
            float d = res[1 + e] - mean;
            var += d * d;
        }
        var *= 0.25f;
        float imp = var / (mean * mean + EPSV);
        if (out_size >= N_TOK * D_IN + 2) {
            out[N_TOK * D_IN]     = l1;
            out[N_TOK * D_IN + 1] = imp;
        }
        int s = 0, ts = 0;
        #pragma unroll
        for (int e = 0; e < NE; e++) {
            g_off[e] = s;
            g_tile_start[e] = ts;
            s  += g_cnt[e];
            ts += (g_cnt[e] + TM - 1) / TM;
        }
        g_off[NE] = s;
        g_tile_start[NE] = ts;
    }
}

// ---------------- 3) scatter ----------------
__global__ void scatter_kernel() {
    int t = blockIdx.x * blockDim.x + threadIdx.x;
    if (t >= N_TOK) return;
    int e = g_gate_idx[t];
    int pos = atomicAdd(&g_cur[e], 1);
    g_perm[g_off[e] + pos] = t;
}

// ---------------- 4/5) fp16 grouped GEMM via mma.sync ----------------
// 128x256 CTA tile, 16 warps (2x8), warp tile 64x32, 4-stage cp.async pipeline.
// FIRST:  H = relu(X[perm] @ W1^T + b1)  (fp16 out)   KDIM=512,  NOUT=1024
// !FIRST: out[tok] = gate * (H @ W2^T + b2)  (f32)    KDIM=1024, NOUT=512
template <int KDIM, int NOUT, bool FIRST>
__global__ __launch_bounds__(NTHREADS, 1) void moe_gemm(const float* __restrict__ BIAS,
                                                        float* __restrict__ OUT)
{
    extern __shared__ char smem[];
    constexpr int NC = KDIM / KC;
    static_assert(NC > STAGES, "pipeline priming assumes NC > STAGES");

    int bt = blockIdx.x;
    if (bt >= g_tile_start[NE]) return;
    int e = 0;
    while (bt >= g_tile_start[e + 1]) e++;
    int m0  = (bt - g_tile_start[e]) * TM;
    int cnt = g_cnt[e];
    int off = g_off[e];
    int n0  = blockIdx.y * TN;

    uint32_t sb = smem_u32(smem);
    int tid = threadIdx.x, wid = tid >> 5, lane = tid & 31;

    if (tid < TM) {
        int am = m0 + tid;
        bool v = am < cnt;
        int tok = v ? g_perm[off + am] : 0;
        long rowb;
        if (FIRST) rowb = (long)tok * (KDIM * 2);
        else       rowb = (long)(off + (v ? am : 0)) * (KDIM * 2);
        ((long*)(smem + SM_ABASE))[tid] = rowb;
        ((int*)(smem + SM_TOK))[tid] = tok;
    }
    if (tid < TN) ((float*)(smem + SM_BIAS))[tid] = BIAS[e * NOUT + n0 + tid];

    const char* A = FIRST ? (const char*)g_xh : (const char*)g_hh;
    const char* B = (FIRST ? (const char*)g_w1h : (const char*)g_w2h)
                    + ((size_t)(e * NOUT + n0)) * (KDIM * 2);
    const long* s_abase = (const long*)(smem + SM_ABASE);

    __syncthreads();   // abase table ready

    int lr = tid >> 3, lseg = tid & 7;   // 64 rows x 8 segs per pass of 512 threads
    auto load_chunk = [&](int c, int s) {
        long k0b = (long)c * (KC * 2);
        uint32_t base = sb + s * STAGE_BYTES;
        #pragma unroll
        for (int i = 0; i < 2; i++) {                 // A: 128 rows
            int r = lr + i * 64;
            uint32_t d = swz(r * 128 + lseg * 16);
            cp_async16(base + d, A + s_abase[r] + k0b + lseg * 16);
        }
        #pragma unroll
        for (int i = 0; i < 4; i++) {                 // B: 256 rows
            int r = lr + i * 64;
            uint32_t d = swz(r * 128 + lseg * 16);
            cp_async16(base + 16384 + d, B + (long)r * (KDIM * 2) + k0b + lseg * 16);
        }
    };

    // prime the FULL pipeline: STAGES chunks (invariant: loop loads c+STAGES)
    #pragma unroll
    for (int i = 0; i < STAGES; i++) {
        load_chunk(i, i);
        CP_COMMIT();
    }

    // warp layout: 2 (M) x 8 (N); warp tile 64x32
    int wm = (wid >> 3) * 64;
    int wn = (wid & 7) * 32;
    int a_row = lane & 15;
    uint32_t a_col = (lane >> 4) * 16;                  // byte
    int b_row = wn + ((lane >> 4) << 3) + (lane & 7);   // + p*16
    uint32_t b_col = ((lane >> 3) & 1) * 16;

    float acc[4][4][4];
    #pragma unroll
    for (int i = 0; i < 4; i++)
        #pragma unroll
        for (int j = 0; j < 4; j++)
            #pragma unroll
            for (int k = 0; k < 4; k++) acc[i][j][k] = 0.f;

    for (int c = 0; c < NC; c++) {
        int s = c % STAGES;
        CP_WAITP();            // <= STAGES-1 pending => chunk c resident
        __syncthreads();
        uint32_t ab = sb + s * STAGE_BYTES;
        uint32_t bb = ab + 16384;

        #pragma unroll
        for (int ks = 0; ks < 4; ks++) {
            uint32_t kb = ks * 32;   // 16 elems * 2B
            uint32_t a[4][4], b[4][2];
            #pragma unroll
            for (int f = 0; f < 4; f++)
                ldsm4(a[f], ab + swz((wm + f * 16 + a_row) * 128 + kb + a_col));
            #pragma unroll
            for (int p = 0; p < 2; p++) {
                uint32_t r[4];
                ldsm4(r, bb + swz((b_row + p * 16) * 128 + kb + b_col));
                b[2 * p][0] = r[0]; b[2 * p][1] = r[1];
                b[2 * p + 1][0] = r[2]; b[2 * p + 1][1] = r[3];
            }
            #pragma unroll
            for (int f = 0; f < 4; f++)
                #pragma unroll
                for (int g = 0; g < 4; g++)
                    mma16816(acc[f][g], a[f], b[g]);
        }
        __syncthreads();
        if (c + STAGES < NC) load_chunk(c + STAGES, s);
        CP_COMMIT();
    }
    CP_WAIT0();

    // ---- epilogue ----
    // acc[f][g][k]: row = wm + f*16 + (k>=2)*8 + lane/4 ; col = wn + g*8 + 2*(lane%4) + (k&1)
    const float* sbias = (const float*)(smem + SM_BIAS);
    const int* s_tok = (const int*)(smem + SM_TOK);
    int rbase = wm + (lane >> 2);
    int cbase = wn + 2 * (lane & 3);

    #pragma unroll
    for (int f = 0; f < 4; f++) {
        #pragma unroll
        for (int half = 0; half < 2; half++) {
            int lrow = rbase + f * 16 + half * 8;
            if (m0 + lrow >= cnt) continue;
            if (FIRST) {
                size_t hrow = (size_t)(off + m0 + lrow) * H_DIM + n0;
                #pragma unroll
                for (int g = 0; g < 4; g++) {
                    int col = cbase + g * 8;
                    float v0 = fmaxf(acc[f][g][2 * half]     + sbias[col],     0.f);
                    float v1 = fmaxf(acc[f][g][2 * half + 1] + sbias[col + 1], 0.f);
                    *(__half2*)(g_hh + hrow + col) = __floats2half2_rn(v0, v1);
                }
            } else {
                int tok = s_tok[lrow];
                float gv = g_gate_val[tok];
                float* orow = OUT + (size_t)tok * D_IN + n0;
                #pragma unroll
                for (int g = 0; g < 4; g++) {
                    int col = cbase + g * 8;
                    float2 o;
                    o.x = (acc[f][g][2 * half]     + sbias[col])     * gv;
                    o.y = (acc[f][g][2 * half + 1] + sbias[col + 1]) * gv;
                    *(float2*)(orow + col) = o;
                }
            }
        }
    }
}

// ---------------- launch ----------------
extern "C" void kernel_launch(void* const* d_in, const int* in_sizes, int n_in,
                              void* d_out, int out_size)
{
    const float* x   = (const float*)d_in[0];
    const float* emb = (const float*)d_in[1];
    const float* rw  = (const float*)d_in[2];
    const float* w1  = (const float*)d_in[3];
    const float* b1  = (const float*)d_in[4];
    const float* w2  = (const float*)d_in[5];
    const float* b2  = (const float*)d_in[6];
    float* out = (float*)d_out;

    cudaFuncSetAttribute(moe_gemm<D_IN, H_DIM, true>,
                         cudaFuncAttributeMaxDynamicSharedMemorySize, SMEM_DYN);
    cudaFuncSetAttribute(moe_gemm<H_DIM, D_IN, false>,
                         cudaFuncAttributeMaxDynamicSharedMemorySize, SMEM_DYN);

    zero_kernel<<<1, 32>>>();
    half_kernel<1><<<512, 256>>>((const float4*)w1, NE * H_DIM * D_IN / 4);
    half_kernel<2><<<512, 256>>>((const float4*)w2, NE * D_IN * H_DIM / 4);
    router_kernel<<<RBLK, 256>>>(x, emb, rw);
    finalize_kernel<<<1, 256>>>(out, out_size);
    scatter_kernel<<<N_TOK / 256, 256>>>();
    moe_gemm<D_IN, H_DIM, true><<<dim3(MAX_TILES, H_DIM / TN), NTHREADS, SMEM_DYN>>>(b1, nullptr);
    moe_gemm<H_DIM, D_IN, false><<<dim3(MAX_TILES, D_IN / TN), NTHREADS, SMEM_DYN>>>(b2, out);
}

// round 11
// speedup vs baseline: 6.8150x; 1.0753x over previous
#include <cuda_runtime.h>
#include <cuda_fp16.h>
#include <cstdint>

// ---------------- Problem constants ----------------
#define N_TOK (16 * 2048)   // 32768 tokens
#define D_IN  512
#define E_DIM 256
#define H_DIM 1024
#define NE    4
#define RIN   (E_DIM + D_IN)
#define EPSV  1e-10f

// ---------------- GEMM tiling ----------------
#define TM 128
#define TN 256
#define KC 64                         // K elements per chunk (64 fp16 = 128B/row)
#define STAGES 4
#define NTHREADS 512
#define MAX_TILES (N_TOK / TM + NE)   // 260 worst-case M-tiles

#define RTOK_PER_BLK 8
#define RBLK (N_TOK / RTOK_PER_BLK)

// ---------------- Shared memory layout ----------------
// Per stage: A 16K | B 32K = 48K
#define STAGE_BYTES 49152
#define SM_BIAS  (STAGES * STAGE_BYTES)          // 196608: 256 floats
#define SM_ABASE (SM_BIAS + 1024)                // 128 x int64 row byte offsets
#define SM_TOK   (SM_ABASE + 1024)               // 128 x int
#define SMEM_DYN (SM_TOK + 512)                  // ~199168 bytes

// ---------------- Device scratch ----------------
__device__ int   g_gate_idx[N_TOK];
__device__ float g_gate_val[N_TOK];
__device__ int   g_perm[N_TOK + 128];
__device__ int   g_cnt[NE];
__device__ int   g_cur[NE];
__device__ int   g_off[NE + 1];
__device__ int   g_tile_start[NE + 1];
__device__ float g_part_l1[RBLK];
__device__ float g_part_imp[RBLK * NE];

__device__ __half g_xh[(size_t)N_TOK * D_IN];
__device__ __half g_w1h[(size_t)NE * H_DIM * D_IN];
__device__ __half g_w2h[(size_t)NE * D_IN * H_DIM];
__device__ __half g_hh[(size_t)(N_TOK + 128) * H_DIM];

// ---------------- PTX helpers (baseline ISA only) ----------------
__device__ __forceinline__ uint32_t smem_u32(const void* p) {
    uint32_t a;
    asm("{ .reg .u64 t; cvta.to.shared.u64 t, %1; cvt.u32.u64 %0, t; }" : "=r"(a) : "l"(p));
    return a;
}
__device__ __forceinline__ void cp_async16(uint32_t dst, const void* src) {
    asm volatile("cp.async.cg.shared.global [%0], [%1], 16;" :: "r"(dst), "l"(src) : "memory");
}
#define CP_COMMIT() asm volatile("cp.async.commit_group;" ::: "memory")
// Wait until at most STAGES-1 groups pending => oldest (current chunk) is resident.
#define CP_WAITP()  asm volatile("cp.async.wait_group 3;" ::: "memory")
#define CP_WAIT0()  asm volatile("cp.async.wait_group 0;" ::: "memory")

__device__ __forceinline__ void ldsm4(uint32_t* r, uint32_t addr) {
    asm volatile("ldmatrix.sync.aligned.m8n8.x4.shared.b16 {%0,%1,%2,%3}, [%4];"
        : "=r"(r[0]), "=r"(r[1]), "=r"(r[2]), "=r"(r[3]) : "r"(addr));
}
__device__ __forceinline__ void mma16816(float* c, const uint32_t* a, const uint32_t* b) {
    asm volatile(
        "mma.sync.aligned.m16n8k16.row.col.f32.f16.f16.f32 "
        "{%0,%1,%2,%3}, {%4,%5,%6,%7}, {%8,%9}, {%0,%1,%2,%3};"
        : "+f"(c[0]), "+f"(c[1]), "+f"(c[2]), "+f"(c[3])
        : "r"(a[0]), "r"(a[1]), "r"(a[2]), "r"(a[3]), "r"(b[0]), "r"(b[1]));
}
__device__ __forceinline__ uint32_t swz(uint32_t b) { return b ^ ((b >> 3) & 0x70); }

// ---------------- 0) convert w1+w2 -> fp16, and reset per-call counters ----------------
__global__ __launch_bounds__(256) void convert_w_kernel(const float4* __restrict__ w1,
                                                        const float4* __restrict__ w2) {
    if (blockIdx.x == 0 && threadIdx.x < NE) {
        g_cnt[threadIdx.x] = 0;
        g_cur[threadIdx.x] = 0;
    }
    const int n4 = NE * H_DIM * D_IN / 4;   // per-weight float4 count (both are same size)
    __half2* h1 = (__half2*)g_w1h;
    __half2* h2 = (__half2*)g_w2h;
    int stride = gridDim.x * blockDim.x;
    for (int i = blockIdx.x * blockDim.x + threadIdx.x; i < 2 * n4; i += stride) {
        if (i < n4) {
            float4 v = w1[i];
            h1[2 * i]     = __floats2half2_rn(v.x, v.y);
            h1[2 * i + 1] = __floats2half2_rn(v.z, v.w);
        } else {
            int j = i - n4;
            float4 v = w2[j];
            h2[2 * j]     = __floats2half2_rn(v.x, v.y);
            h2[2 * j + 1] = __floats2half2_rn(v.z, v.w);
        }
    }
}

// ---------------- 1) router (transposed weights, fused x -> fp16) ----------------
__global__ __launch_bounds__(256) void router_kernel(
    const float* __restrict__ x, const float* __restrict__ emb,
    const float* __restrict__ rw)
{
    __shared__ float s_rwt[NE][RIN];    // transposed: conflict-free lane-consecutive reads
    __shared__ float s_l1[RTOK_PER_BLK];
    __shared__ float s_imp[RTOK_PER_BLK][NE];

    int t = threadIdx.x;
    for (int i = t; i < RIN * NE; i += blockDim.x) {
        int e = i / RIN, k = i % RIN;
        s_rwt[e][k] = rw[k * NE + e];
    }
    __syncthreads();

    int warp = t >> 5, lane = t & 31;
    int tok = blockIdx.x * RTOK_PER_BLK + warp;

    float acc0 = 0.f, acc1 = 0.f, acc2 = 0.f, acc3 = 0.f;
    const float4* er4 = (const float4*)(emb + (size_t)tok * E_DIM);
    const float4* xr4 = (const float4*)(x   + (size_t)tok * D_IN);
    __half2* xh2 = (__half2*)(g_xh + (size_t)tok * D_IN);

    const float* w0 = s_rwt[0];
    const float* w1 = s_rwt[1];
    const float* w2 = s_rwt[2];
    const float* w3 = s_rwt[3];

    // embed part: E_DIM/4 = 64 float4 per token, 2 per lane
    #pragma unroll
    for (int i = 0; i < E_DIM / 128; i++) {
        int q = lane + 32 * i;
        float4 v = er4[q];
        int k = 4 * q;
        acc0 += v.x * w0[k] + v.y * w0[k + 1] + v.z * w0[k + 2] + v.w * w0[k + 3];
        acc1 += v.x * w1[k] + v.y * w1[k + 1] + v.z * w1[k + 2] + v.w * w1[k + 3];
        acc2 += v.x * w2[k] + v.y * w2[k + 1] + v.z * w2[k + 2] + v.w * w2[k + 3];
        acc3 += v.x * w3[k] + v.y * w3[k + 1] + v.z * w3[k + 2] + v.w * w3[k + 3];
    }
    // inputs part: D_IN/4 = 128 float4 per token, 4 per lane; fused fp16 convert
    #pragma unroll
    for (int i = 0; i < D_IN / 128; i++) {
        int q = lane + 32 * i;
        float4 v = xr4[q];
        int k = E_DIM + 4 * q;
        acc0 += v.x * w0[k] + v.y * w0[k + 1] + v.z * w0[k + 2] + v.w * w0[k + 3];
        acc1 += v.x * w1[k] + v.y * w1[k + 1] + v.z * w1[k + 2] + v.w * w1[k + 3];
        acc2 += v.x * w2[k] + v.y * w2[k + 1] + v.z * w2[k + 2] + v.w * w2[k + 3];
        acc3 += v.x * w3[k] + v.y * w3[k + 1] + v.z * w3[k + 2] + v.w * w3[k + 3];
        xh2[2 * q]     = __floats2half2_rn(v.x, v.y);
        xh2[2 * q + 1] = __floats2half2_rn(v.z, v.w);
    }

    #pragma unroll
    for (int o = 16; o; o >>= 1) {
        acc0 += __shfl_xor_sync(0xFFFFFFFFu, acc0, o);
        acc1 += __shfl_xor_sync(0xFFFFFFFFu, acc1, o);
        acc2 += __shfl_xor_sync(0xFFFFFFFFu, acc2, o);
        acc3 += __shfl_xor_sync(0xFFFFFFFFu, acc3, o);
    }

    if (lane == 0) {
        float lg[NE] = {acc0, acc1, acc2, acc3};
        float m = lg[0];
        #pragma unroll
        for (int e = 1; e < NE; e++) m = fmaxf(m, lg[e]);
        float p[NE], s = 0.f;
        #pragma unroll
        for (int e = 0; e < NE; e++) { p[e] = __expf(lg[e] - m); s += p[e]; }
        float inv = 1.f / s;
        float sump = 0.f, sq = 0.f;
        float best = -1.f; int bi = 0;
        #pragma unroll
        for (int e = 0; e < NE; e++) {
            p[e] *= inv;
            sump += p[e];
            sq   += p[e] * p[e];
            if (p[e] > best) { best = p[e]; bi = e; }
        }
        g_gate_idx[tok] = bi;
        g_gate_val[tok] = best;
        atomicAdd(&g_cnt[bi], 1);
        s_l1[warp] = sump / (sqrtf(sq) + EPSV);
        #pragma unroll
        for (int e = 0; e < NE; e++) s_imp[warp][e] = p[e];
    }
    __syncthreads();
    if (t == 0) {
        float a = 0.f;
        #pragma unroll
        for (int w = 0; w < RTOK_PER_BLK; w++) a += s_l1[w];
        g_part_l1[blockIdx.x] = a;
    }
    if (t < NE) {
        float a = 0.f;
        #pragma unroll
        for (int w = 0; w < RTOK_PER_BLK; w++) a += s_imp[w][t];
        g_part_imp[blockIdx.x * NE + t] = a;
    }
}

// ---------------- 2) finalize ----------------
__global__ void finalize_kernel(float* __restrict__ out, int out_size) {
    __shared__ float sh[256];
    int t = threadIdx.x;
    float v[5] = {0.f, 0.f, 0.f, 0.f, 0.f};
    for (int b = t; b < RBLK; b += 256) {
        v[0] += g_part_l1[b];
        #pragma unroll
        for (int e = 0; e < NE; e++) v[1 + e] += g_part_imp[b * NE + e];
    }
    float res[5];
    #pragma unroll
    for (int q = 0; q < 5; q++) {
        sh[t] = v[q]; __syncthreads();
        for (int s = 128; s; s >>= 1) {
            if (t < s) sh[t] += sh[t + s];
            __syncthreads();
        }
        res[q] = sh[0];
        __syncthreads();
    }
    if (t == 0) {
        float l1 = res[0] / (float)N_TOK;
        float mean = (res[1] + res[2] + res[3] + res[4]) * 0.25f;
        float var = 0.f;
        #pragma unroll
        for (int e = 0; e < NE; e++) {
            float d = res[1 + e] - mean;
            var += d * d;
        }
        var *= 0.25f;
        float imp = var / (mean * mean + EPSV);
        if (out_size >= N_TOK * D_IN + 2) {
            out[N_TOK * D_IN]     = l1;
            out[N_TOK * D_IN + 1] = imp;
        }
        int s = 0, ts = 0;
        #pragma unroll
        for (int e = 0; e < NE; e++) {
            g_off[e] = s;
            g_tile_start[e] = ts;
            s  += g_cnt[e];
            ts += (g_cnt[e] + TM - 1) / TM;
        }
        g_off[NE] = s;
        g_tile_start[NE] = ts;
    }
}

// ---------------- 3) scatter (warp-aggregated atomics) ----------------
__global__ void scatter_kernel() {
    int t = blockIdx.x * blockDim.x + threadIdx.x;
    int lane = threadIdx.x & 31;
    int e = g_gate_idx[t];        // grid is exact multiple of N_TOK
    #pragma unroll
    for (int ei = 0; ei < NE; ei++) {
        unsigned m = __ballot_sync(0xFFFFFFFFu, e == ei);
        if (e == ei) {
            int leader = __ffs(m) - 1;
            int rank = __popc(m & ((1u << lane) - 1));
            int base = 0;
            if (lane == leader) base = atomicAdd(&g_cur[ei], __popc(m));
            base = __shfl_sync(m, base, leader);
            g_perm[g_off[ei] + base + rank] = t;
        }
    }
}

// ---------------- 4/5) fp16 grouped GEMM via mma.sync ----------------
// 128x256 CTA tile, 16 warps (2x8), warp tile 64x32, 4-stage cp.async pipeline.
// FIRST:  H = relu(X[perm] @ W1^T + b1)  (fp16 out)   KDIM=512,  NOUT=1024
// !FIRST: out[tok] = gate * (H @ W2^T + b2)  (f32)    KDIM=1024, NOUT=512
template <int KDIM, int NOUT, bool FIRST>
__global__ __launch_bounds__(NTHREADS, 1) void moe_gemm(const float* __restrict__ BIAS,
                                                        float* __restrict__ OUT)
{
    extern __shared__ char smem[];
    constexpr int NC = KDIM / KC;
    static_assert(NC > STAGES, "pipeline priming assumes NC > STAGES");

    int bt = blockIdx.x;
    if (bt >= g_tile_start[NE]) return;
    int e = 0;
    while (bt >= g_tile_start[e + 1]) e++;
    int m0  = (bt - g_tile_start[e]) * TM;
    int cnt = g_cnt[e];
    int off = g_off[e];
    int n0  = blockIdx.y * TN;

    uint32_t sb = smem_u32(smem);
    int tid = threadIdx.x, wid = tid >> 5, lane = tid & 31;

    if (tid < TM) {
        int am = m0 + tid;
        bool v = am < cnt;
        int tok = v ? g_perm[off + am] : 0;
        long rowb;
        if (FIRST) rowb = (long)tok * (KDIM * 2);
        else       rowb = (long)(off + (v ? am : 0)) * (KDIM * 2);
        ((long*)(smem + SM_ABASE))[tid] = rowb;
        ((int*)(smem + SM_TOK))[tid] = tok;
    }
    if (tid < TN) ((float*)(smem + SM_BIAS))[tid] = BIAS[e * NOUT + n0 + tid];

    const char* A = FIRST ? (const char*)g_xh : (const char*)g_hh;
    const char* B = (FIRST ? (const char*)g_w1h : (const char*)g_w2h)
                    + ((size_t)(e * NOUT + n0)) * (KDIM * 2);
    const long* s_abase = (const long*)(smem + SM_ABASE);

    __syncthreads();   // abase table ready

    int lr = tid >> 3, lseg = tid & 7;   // 64 rows x 8 segs per pass of 512 threads
    auto load_chunk = [&](int c, int s) {
        long k0b = (long)c * (KC * 2);
        uint32_t base = sb + s * STAGE_BYTES;
        #pragma unroll
        for (int i = 0; i < 2; i++) {                 // A: 128 rows
            int r = lr + i * 64;
            uint32_t d = swz(r * 128 + lseg * 16);
            cp_async16(base + d, A + s_abase[r] + k0b + lseg * 16);
        }
        #pragma unroll
        for (int i = 0; i < 4; i++) {                 // B: 256 rows
            int r = lr + i * 64;
            uint32_t d = swz(r * 128 + lseg * 16);
            cp_async16(base + 16384 + d, B + (long)r * (KDIM * 2) + k0b + lseg * 16);
        }
    };

    // prime the FULL pipeline: STAGES chunks (invariant: loop loads c+STAGES)
    #pragma unroll
    for (int i = 0; i < STAGES; i++) {
        load_chunk(i, i);
        CP_COMMIT();
    }

    // warp layout: 2 (M) x 8 (N); warp tile 64x32
    int wm = (wid >> 3) * 64;
    int wn = (wid & 7) * 32;
    int a_row = lane & 15;
    uint32_t a_col = (lane >> 4) * 16;                  // byte
    int b_row = wn + ((lane >> 4) << 3) + (lane & 7);   // + p*16
    uint32_t b_col = ((lane >> 3) & 1) * 16;

    float acc[4][4][4];
    #pragma unroll
    for (int i = 0; i < 4; i++)
        #pragma unroll
        for (int j = 0; j < 4; j++)
            #pragma unroll
            for (int k = 0; k < 4; k++) acc[i][j][k] = 0.f;

    for (int c = 0; c < NC; c++) {
        int s = c % STAGES;
        CP_WAITP();            // <= STAGES-1 pending => chunk c resident
        __syncthreads();
        uint32_t ab = sb + s * STAGE_BYTES;
        uint32_t bb = ab + 16384;

        #pragma unroll
        for (int ks = 0; ks < 4; ks++) {
            uint32_t kb = ks * 32;   // 16 elems * 2B
            uint32_t a[4][4], b[4][2];
            #pragma unroll
            for (int f = 0; f < 4; f++)
                ldsm4(a[f], ab + swz((wm + f * 16 + a_row) * 128 + kb + a_col));
            #pragma unroll
            for (int p = 0; p < 2; p++) {
                uint32_t r[4];
                ldsm4(r, bb + swz((b_row + p * 16) * 128 + kb + b_col));
                b[2 * p][0] = r[0]; b[2 * p][1] = r[1];
                b[2 * p + 1][0] = r[2]; b[2 * p + 1][1] = r[3];
            }
            #pragma unroll
            for (int f = 0; f < 4; f++)
                #pragma unroll
                for (int g = 0; g < 4; g++)
                    mma16816(acc[f][g], a[f], b[g]);
        }
        __syncthreads();
        if (c + STAGES < NC) load_chunk(c + STAGES, s);
        CP_COMMIT();
    }
    CP_WAIT0();

    // ---- epilogue ----
    // acc[f][g][k]: row = wm + f*16 + (k>=2)*8 + lane/4 ; col = wn + g*8 + 2*(lane%4) + (k&1)
    const float* sbias = (const float*)(smem + SM_BIAS);
    const int* s_tok = (const int*)(smem + SM_TOK);
    int rbase = wm + (lane >> 2);
    int cbase = wn + 2 * (lane & 3);

    #pragma unroll
    for (int f = 0; f < 4; f++) {
        #pragma unroll
        for (int half = 0; half < 2; half++) {
            int lrow = rbase + f * 16 + half * 8;
            if (m0 + lrow >= cnt) continue;
            if (FIRST) {
                size_t hrow = (size_t)(off + m0 + lrow) * H_DIM + n0;
                #pragma unroll
                for (int g = 0; g < 4; g++) {
                    int col = cbase + g * 8;
                    float v0 = fmaxf(acc[f][g][2 * half]     + sbias[col],     0.f);
                    float v1 = fmaxf(acc[f][g][2 * half + 1] + sbias[col + 1], 0.f);
                    *(__half2*)(g_hh + hrow + col) = __floats2half2_rn(v0, v1);
                }
            } else {
                int tok = s_tok[lrow];
                float gv = g_gate_val[tok];
                float* orow = OUT + (size_t)tok * D_IN + n0;
                #pragma unroll
                for (int g = 0; g < 4; g++) {
                    int col = cbase + g * 8;
                    float2 o;
                    o.x = (acc[f][g][2 * half]     + sbias[col])     * gv;
                    o.y = (acc[f][g][2 * half + 1] + sbias[col + 1]) * gv;
                    *(float2*)(orow + col) = o;
                }
            }
        }
    }
}

// ---------------- launch ----------------
extern "C" void kernel_launch(void* const* d_in, const int* in_sizes, int n_in,
                              void* d_out, int out_size)
{
    const float* x   = (const float*)d_in[0];
    const float* emb = (const float*)d_in[1];
    const float* rw  = (const float*)d_in[2];
    const float* w1  = (const float*)d_in[3];
    const float* b1  = (const float*)d_in[4];
    const float* w2  = (const float*)d_in[5];
    const float* b2  = (const float*)d_in[6];
    float* out = (float*)d_out;

    cudaFuncSetAttribute(moe_gemm<D_IN, H_DIM, true>,
                         cudaFuncAttributeMaxDynamicSharedMemorySize, SMEM_DYN);
    cudaFuncSetAttribute(moe_gemm<H_DIM, D_IN, false>,
                         cudaFuncAttributeMaxDynamicSharedMemorySize, SMEM_DYN);

    convert_w_kernel<<<1024, 256>>>((const float4*)w1, (const float4*)w2);
    router_kernel<<<RBLK, 256>>>(x, emb, rw);
    finalize_kernel<<<1, 256>>>(out, out_size);
    scatter_kernel<<<N_TOK / 256, 256>>>();
    moe_gemm<D_IN, H_DIM, true><<<dim3(MAX_TILES, H_DIM / TN), NTHREADS, SMEM_DYN>>>(b1, nullptr);
    moe_gemm<H_DIM, D_IN, false><<<dim3(MAX_TILES, D_IN / TN), NTHREADS, SMEM_DYN>>>(b2, out);
}